// round 12
// baseline (speedup 1.0000x reference)
#include <cuda_runtime.h>
#include <cuda_fp16.h>
#include <cstdint>

// Round 12: R11 + (a) tanh.approx.f32 for expert outputs (final tanh exact),
// (b) softmax without max-shift (logits bounded), (c) ldmatrix prefetch in
// the expert mainloop. Everything fp16 mma; expert weights register-resident.
// CTA = 256 threads = 8 warps (warp e = expert e), tile = 256 tokens.

#define NTILES 4096
#define GRID   592

typedef unsigned int u32;

// pack two floats to f16x2: low half = lo, high half = hi
__device__ __forceinline__ u32 f16pk(float lo, float hi) {
    u32 d; asm("cvt.rn.f16x2.f32 %0,%1,%2;" : "=r"(d) : "f"(hi), "f"(lo)); return d;
}
// packed relu: round pair to fp16, then max with +0
__device__ __forceinline__ u32 relu_pk(float lo, float hi) {
    u32 d = f16pk(lo, hi);
    u32 r; asm("max.f16x2 %0,%1,%2;" : "=r"(r) : "r"(d), "r"(0u)); return r;
}
// exact-ish tanh for final output
__device__ __forceinline__ float tanh_acc(float v) {
    float e = __expf(2.0f * v);
    return 1.0f - __fdividef(2.0f, e + 1.0f);
}
// hardware tanh (MUFU.TANH) for intermediate expert outputs
__device__ __forceinline__ float tanh_fast(float v) {
    float r; asm("tanh.approx.f32 %0,%1;" : "=f"(r) : "f"(v)); return r;
}

// ---------------- mma / ldmatrix ----------------
__device__ __forceinline__ void mma_f16_c(float& d0, float& d1, float& d2, float& d3,
                                          u32 a0, u32 a1, u32 a2, u32 a3,
                                          u32 b0, u32 b1, float c0, float c1) {
    asm volatile("mma.sync.aligned.m16n8k16.row.col.f32.f16.f16.f32 "
                 "{%0,%1,%2,%3},{%4,%5,%6,%7},{%8,%9},{%10,%11,%10,%11};"
                 : "=f"(d0), "=f"(d1), "=f"(d2), "=f"(d3)
                 : "r"(a0), "r"(a1), "r"(a2), "r"(a3), "r"(b0), "r"(b1),
                   "f"(c0), "f"(c1));
}
__device__ __forceinline__ void mma_f16_acc(float& d0, float& d1, float& d2, float& d3,
                                            u32 a0, u32 a1, u32 a2, u32 a3,
                                            u32 b0, u32 b1) {
    asm volatile("mma.sync.aligned.m16n8k16.row.col.f32.f16.f16.f32 "
                 "{%0,%1,%2,%3},{%4,%5,%6,%7},{%8,%9},{%0,%1,%2,%3};"
                 : "+f"(d0), "+f"(d1), "+f"(d2), "+f"(d3)
                 : "r"(a0), "r"(a1), "r"(a2), "r"(a3), "r"(b0), "r"(b1));
}
__device__ __forceinline__ void ldm_x4(u32* r, u32 addr) {
    asm volatile("ldmatrix.sync.aligned.m8n8.x4.shared.b16 {%0,%1,%2,%3}, [%4];"
                 : "=r"(r[0]), "=r"(r[1]), "=r"(r[2]), "=r"(r[3]) : "r"(addr));
}
__device__ __forceinline__ u32 smem_to_u32(const void* p) {
    u32 a;
    asm("{ .reg .u64 t; cvta.to.shared.u64 t, %1; cvt.u32.u64 %0, t; }" : "=r"(a) : "l"(p));
    return a;
}

// ---------------- SMEM layout (bytes) ----------------
#define XB  0        // x fp16 rows: 256 x 48B
#define RB  12288    // rin fp16 rows: 256 x 48B
#define WX  24576    // normalized gate weights [8][256] f32   (8 KB)
#define FU  32768    // expert outputs (unweighted tanh) [8][256] float2 (16 KB)
#define TB2 49152    // expert bias2 table [e][nt][tig] float2  (1 KB)
#define GT  50176    // gate lane tables: 32 x 272B
#define RT  58880    // refine lane tables: 32 x 272B
#define SMEM_TOTAL 67584

extern __shared__ char smem_raw[];

__global__ void __launch_bounds__(256, 2)
moe_r12_kernel(const float* __restrict__ X,
               const float* __restrict__ W1, const float* __restrict__ b1,
               const float* __restrict__ W2, const float* __restrict__ b2,
               const float* __restrict__ W3, const float* __restrict__ b3,
               const float* __restrict__ G1, const float* __restrict__ gb1,
               const float* __restrict__ G2, const float* __restrict__ gb2,
               const float* __restrict__ R1, const float* __restrict__ rb1,
               const float* __restrict__ R2, const float* __restrict__ rb2,
               float* __restrict__ out)
{
    const int tid  = threadIdx.x;
    const int wid  = tid >> 5;     // = expert id
    const int lane = tid & 31;
    const int grp  = lane >> 2;
    const int tig  = lane & 3;
    const u32 sbase = smem_to_u32(smem_raw);

    // ---- expert bias2 broadcast table ----
    if (tid < 128) {
        int te = tid >> 4, tn = (tid >> 2) & 3, tg = tid & 3;
        int c0 = tn * 8 + 2 * tg;
        *reinterpret_cast<float2*>(smem_raw + TB2 + tid * 8) =
            make_float2(b2[te * 32 + c0], b2[te * 32 + c0 + 1]);
    }

    // ---- gate / refine per-lane fragment tables (272B stride, conflict-free) ----
    if (tid < 32) {
        int g = tid >> 2, t = tid & 3;
        int k0 = 2 * t;
        {
            char* gt = smem_raw + GT + tid * 272;
            u32*    b1t = reinterpret_cast<u32*>(gt);
            float2* c1t = reinterpret_cast<float2*>(gt + 64);
            u32*    b2t = reinterpret_cast<u32*>(gt + 128);
            float2* c2t = reinterpret_cast<float2*>(gt + 160);
            #pragma unroll
            for (int nt = 0; nt < 8; nt++) {
                int n = nt * 8 + g;
                b1t[nt * 2]     = f16pk(G1[k0 * 64 + n], G1[(k0 + 1) * 64 + n]);
                float wa = (k0 + 8 < 10) ? G1[(k0 + 8) * 64 + n] : 0.f;
                float wb = (k0 + 9 < 10) ? G1[(k0 + 9) * 64 + n] : 0.f;
                b1t[nt * 2 + 1] = f16pk(wa, wb);
                c1t[nt] = make_float2(gb1[nt * 8 + k0], gb1[nt * 8 + k0 + 1]);
            }
            #pragma unroll
            for (int kt = 0; kt < 4; kt++) {
                int kk = kt * 16 + k0;
                b2t[kt * 2]     = f16pk(G2[kk * 8 + g],       G2[(kk + 1) * 8 + g]);
                b2t[kt * 2 + 1] = f16pk(G2[(kk + 8) * 8 + g], G2[(kk + 9) * 8 + g]);
            }
            c2t[0] = make_float2(gb2[k0], gb2[k0 + 1]);
        }
        {
            char* rt = smem_raw + RT + tid * 272;
            u32*    b1t = reinterpret_cast<u32*>(rt);
            float2* c1t = reinterpret_cast<float2*>(rt + 64);
            u32*    b2t = reinterpret_cast<u32*>(rt + 128);
            float2* c2t = reinterpret_cast<float2*>(rt + 160);
            #pragma unroll
            for (int nt = 0; nt < 8; nt++) {
                int n = nt * 8 + g;
                b1t[nt * 2]     = f16pk(R1[k0 * 64 + n], R1[(k0 + 1) * 64 + n]);
                float wa = (k0 + 8 < 12) ? R1[(k0 + 8) * 64 + n] : 0.f;
                float wb = (k0 + 9 < 12) ? R1[(k0 + 9) * 64 + n] : 0.f;
                b1t[nt * 2 + 1] = f16pk(wa, wb);
                c1t[nt] = make_float2(rb1[nt * 8 + k0], rb1[nt * 8 + k0 + 1]);
            }
            #pragma unroll
            for (int kt = 0; kt < 4; kt++) {
                int kk = kt * 16 + k0;
                float wa0 = (g < 2) ? R2[kk * 2 + g] : 0.f;
                float wb0 = (g < 2) ? R2[(kk + 1) * 2 + g] : 0.f;
                b2t[kt * 2]     = f16pk(wa0, wb0);
                float wa1 = (g < 2) ? R2[(kk + 8) * 2 + g] : 0.f;
                float wb1 = (g < 2) ? R2[(kk + 9) * 2 + g] : 0.f;
                b2t[kt * 2 + 1] = f16pk(wa1, wb1);
            }
            c2t[0] = make_float2(t == 0 ? rb2[0] : 0.f, t == 0 ? rb2[1] : 0.f);
        }
    }

    // ---- register-resident fp16 expert fragments (warp e = expert e) ----
    const int e = wid;
    u32 b1f[4][2];            // W1 [nt][b0/b1]
    u32 b2f[4][2][2];         // W2 [nt][kt][b0/b1]
    u32 w3f[2][2];            // W3 [kc][b0/b1], n = grp (zero for grp >= 2)
    float bias1[4][2];
    #pragma unroll
    for (int nt = 0; nt < 4; nt++) {
        int n = nt * 8 + grp;
        b1f[nt][0] = f16pk(W1[e * 320 + (2 * tig) * 32 + n],
                           W1[e * 320 + (2 * tig + 1) * 32 + n]);
        {
            float wa = (2 * tig + 8 < 10) ? W1[e * 320 + (2 * tig + 8) * 32 + n] : 0.f;
            float wb = (2 * tig + 9 < 10) ? W1[e * 320 + (2 * tig + 9) * 32 + n] : 0.f;
            b1f[nt][1] = f16pk(wa, wb);
        }
        #pragma unroll
        for (int kt = 0; kt < 2; kt++) {
            int k0 = kt * 16 + 2 * tig;
            b2f[nt][kt][0] = f16pk(W2[e * 1024 + k0 * 32 + n],
                                   W2[e * 1024 + (k0 + 1) * 32 + n]);
            b2f[nt][kt][1] = f16pk(W2[e * 1024 + (k0 + 8) * 32 + n],
                                   W2[e * 1024 + (k0 + 9) * 32 + n]);
        }
        int c0 = nt * 8 + 2 * tig;
        bias1[nt][0] = b1[e * 32 + c0];
        bias1[nt][1] = b1[e * 32 + c0 + 1];
    }
    #pragma unroll
    for (int kc = 0; kc < 2; kc++) {
        int kb = kc * 16;
        float v00 = (grp < 2) ? W3[e * 64 + (kb + 2 * tig) * 2 + grp] : 0.f;
        float v01 = (grp < 2) ? W3[e * 64 + (kb + 2 * tig + 1) * 2 + grp] : 0.f;
        w3f[kc][0] = f16pk(v00, v01);
        float v10 = (grp < 2) ? W3[e * 64 + (kb + 8 + 2 * tig) * 2 + grp] : 0.f;
        float v11 = (grp < 2) ? W3[e * 64 + (kb + 9 + 2 * tig) * 2 + grp] : 0.f;
        w3f[kc][1] = f16pk(v10, v11);
    }
    const float b3e0 = b3[e * 2], b3e1 = b3[e * 2 + 1];
    __syncthreads();

    for (int tile = blockIdx.x; tile < NTILES; tile += gridDim.x) {
        const int tok = tile * 256 + tid;

        // ============ phase 1: load x, stage fp16 rows ============
        u32 xs[5];
        {
            const float2* xp = reinterpret_cast<const float2*>(X + (size_t)tok * 10);
            #pragma unroll
            for (int i = 0; i < 5; i++) {
                float2 v = xp[i];
                xs[i] = f16pk(v.x, v.y);
            }
            uint4* p = reinterpret_cast<uint4*>(smem_raw + XB + tid * 48);
            p[0] = make_uint4(xs[0], xs[1], xs[2], xs[3]);
            p[1] = make_uint4(xs[4], 0u, 0u, 0u);
        }
        __syncthreads();

        // ============ phase 2a: gate via mma (2 m-tiles per warp) ============
        {
            const char* gt = smem_raw + GT + (u32)lane * 272;
            const u32*    b1t = reinterpret_cast<const u32*>(gt);
            const float2* c1t = reinterpret_cast<const float2*>(gt + 64);
            const u32*    b2t = reinterpret_cast<const u32*>(gt + 128);
            const float2  c2  = *reinterpret_cast<const float2*>(gt + 160);
            float* wxp = reinterpret_cast<float*>(smem_raw + WX);
            #pragma unroll 1
            for (int q = 0; q < 2; q++) {
                int mt = wid * 2 + q;
                u32 ax[4];
                ldm_x4(ax, sbase + XB + (u32)(mt * 16 + (lane & 15)) * 48
                           + ((lane >> 4) << 4));
                float d[8][4];
                #pragma unroll
                for (int nt = 0; nt < 8; nt++) {
                    float2 cc = c1t[nt];
                    mma_f16_c(d[nt][0], d[nt][1], d[nt][2], d[nt][3],
                              ax[0], ax[1], ax[2], ax[3],
                              b1t[2*nt], b1t[2*nt+1], cc.x, cc.y);
                }
                u32 a2[4][4];
                #pragma unroll
                for (int kt = 0; kt < 4; kt++) {
                    a2[kt][0] = relu_pk(d[2*kt][0],   d[2*kt][1]);
                    a2[kt][1] = relu_pk(d[2*kt][2],   d[2*kt][3]);
                    a2[kt][2] = relu_pk(d[2*kt+1][0], d[2*kt+1][1]);
                    a2[kt][3] = relu_pk(d[2*kt+1][2], d[2*kt+1][3]);
                }
                float l0, l1, l2, l3;
                mma_f16_c(l0, l1, l2, l3,
                          a2[0][0], a2[0][1], a2[0][2], a2[0][3],
                          b2t[0], b2t[1], c2.x, c2.y);
                #pragma unroll
                for (int kt = 1; kt < 4; kt++)
                    mma_f16_acc(l0, l1, l2, l3,
                                a2[kt][0], a2[kt][1], a2[kt][2], a2[kt][3],
                                b2t[2*kt], b2t[2*kt+1]);
                // softmax per row (logits bounded ~|1|: no max-shift needed)
                float eA0 = __expf(l0), eA1 = __expf(l1);
                float sA = eA0 + eA1;
                sA += __shfl_xor_sync(0xFFFFFFFFu, sA, 1);
                sA += __shfl_xor_sync(0xFFFFFFFFu, sA, 2);
                float iA = __fdividef(1.f, sA);
                float eB0 = __expf(l2), eB1 = __expf(l3);
                float sB = eB0 + eB1;
                sB += __shfl_xor_sync(0xFFFFFFFFu, sB, 1);
                sB += __shfl_xor_sync(0xFFFFFFFFu, sB, 2);
                float iB = __fdividef(1.f, sB);
                int rowA = mt * 16 + grp;
                wxp[(2*tig)   * 256 + rowA]     = eA0 * iA;
                wxp[(2*tig+1) * 256 + rowA]     = eA1 * iA;
                wxp[(2*tig)   * 256 + rowA + 8] = eB0 * iB;
                wxp[(2*tig+1) * 256 + rowA + 8] = eB1 * iB;
            }
        }

        // ============ phase 2b: expert GEMMs (warp = expert, 16 m-tiles) ============
        {
            float2* fup = reinterpret_cast<float2*>(smem_raw + FU);
            const u32 xaddr0 = sbase + XB + (u32)(lane & 15) * 48 + ((lane >> 4) << 4);
            u32 axc[4];
            ldm_x4(axc, xaddr0);
            #pragma unroll 1
            for (int mt = 0; mt < 16; mt++) {
                // prefetch next m-tile's A-fragments
                u32 axn[4];
                if (mt < 15)
                    ldm_x4(axn, xaddr0 + (u32)((mt + 1) * 16) * 48);
                // L1 (bias in C)
                float d[4][4];
                #pragma unroll
                for (int nt = 0; nt < 4; nt++)
                    mma_f16_c(d[nt][0], d[nt][1], d[nt][2], d[nt][3],
                              axc[0], axc[1], axc[2], axc[3],
                              b1f[nt][0], b1f[nt][1], bias1[nt][0], bias1[nt][1]);
                // packed relu -> L2 A-frags
                u32 a2[2][4];
                #pragma unroll
                for (int nt = 0; nt < 4; nt++) {
                    int kt = nt >> 1, hf = (nt & 1) << 1;
                    a2[kt][hf]     = relu_pk(d[nt][0], d[nt][1]);
                    a2[kt][hf + 1] = relu_pk(d[nt][2], d[nt][3]);
                }
                // L2 (bias2 from table via C)
                float g[4][4];
                #pragma unroll
                for (int nt = 0; nt < 4; nt++) {
                    float2 tb = *reinterpret_cast<const float2*>(
                        smem_raw + TB2 + (u32)(((e * 4 + nt) * 4 + tig)) * 8);
                    mma_f16_c(g[nt][0], g[nt][1], g[nt][2], g[nt][3],
                              a2[0][0], a2[0][1], a2[0][2], a2[0][3],
                              b2f[nt][0][0], b2f[nt][0][1], tb.x, tb.y);
                    mma_f16_acc(g[nt][0], g[nt][1], g[nt][2], g[nt][3],
                                a2[1][0], a2[1][1], a2[1][2], a2[1][3],
                                b2f[nt][1][0], b2f[nt][1][1]);
                }
                // packed relu -> L3 A-frags
                u32 p3[4][2];
                #pragma unroll
                for (int nt = 0; nt < 4; nt++) {
                    p3[nt][0] = relu_pk(g[nt][0], g[nt][1]);
                    p3[nt][1] = relu_pk(g[nt][2], g[nt][3]);
                }
                // L3 via mma pair (bias3 in C); valid cols 0,1 land on tig==0
                float y0, y1, y2, y3;
                mma_f16_c(y0, y1, y2, y3,
                          p3[0][0], p3[0][1], p3[1][0], p3[1][1],
                          w3f[0][0], w3f[0][1], b3e0, b3e1);
                mma_f16_acc(y0, y1, y2, y3,
                            p3[2][0], p3[2][1], p3[3][0], p3[3][1],
                            w3f[1][0], w3f[1][1]);
                if (tig == 0) {
                    int tk = mt * 16 + grp;
                    fup[e * 256 + tk]     = make_float2(tanh_fast(y0), tanh_fast(y1));
                    fup[e * 256 + tk + 8] = make_float2(tanh_fast(y2), tanh_fast(y3));
                }
                axc[0] = axn[0]; axc[1] = axn[1]; axc[2] = axn[2]; axc[3] = axn[3];
            }
        }
        __syncthreads();

        // ============ phase 3: fuse + restage rin ============
        {
            const float2* fup = reinterpret_cast<const float2*>(smem_raw + FU);
            const float* wxp = reinterpret_cast<const float*>(smem_raw + WX);
            float f0 = 0.f, f1 = 0.f;
            #pragma unroll
            for (int q2 = 0; q2 < 8; q2++) {
                float2 s = fup[q2 * 256 + tid];
                float w = wxp[q2 * 256 + tid];
                f0 += w * s.x; f1 += w * s.y;
            }
            uint4* p = reinterpret_cast<uint4*>(smem_raw + RB + tid * 48);
            p[0] = make_uint4(f16pk(f0, f1), xs[0], xs[1], xs[2]);
            p[1] = make_uint4(xs[3], xs[4], 0u, 0u);
        }
        __syncthreads();

        // ============ phase 4: refine via mma (2 m-tiles per warp) ============
        {
            const char* rt = smem_raw + RT + (u32)lane * 272;
            const u32*    b1t = reinterpret_cast<const u32*>(rt);
            const float2* c1t = reinterpret_cast<const float2*>(rt + 64);
            const u32*    b2t = reinterpret_cast<const u32*>(rt + 128);
            const float2  c2  = *reinterpret_cast<const float2*>(rt + 160);
            float2* out2 = reinterpret_cast<float2*>(out);
            #pragma unroll 1
            for (int q = 0; q < 2; q++) {
                int mt = wid * 2 + q;
                u32 ax[4];
                ldm_x4(ax, sbase + RB + (u32)(mt * 16 + (lane & 15)) * 48
                           + ((lane >> 4) << 4));
                float d[8][4];
                #pragma unroll
                for (int nt = 0; nt < 8; nt++) {
                    float2 cc = c1t[nt];
                    mma_f16_c(d[nt][0], d[nt][1], d[nt][2], d[nt][3],
                              ax[0], ax[1], ax[2], ax[3],
                              b1t[2*nt], b1t[2*nt+1], cc.x, cc.y);
                }
                u32 a2[4][4];
                #pragma unroll
                for (int kt = 0; kt < 4; kt++) {
                    a2[kt][0] = relu_pk(d[2*kt][0],   d[2*kt][1]);
                    a2[kt][1] = relu_pk(d[2*kt][2],   d[2*kt][3]);
                    a2[kt][2] = relu_pk(d[2*kt+1][0], d[2*kt+1][1]);
                    a2[kt][3] = relu_pk(d[2*kt+1][2], d[2*kt+1][3]);
                }
                float y0, y1, y2, y3;
                mma_f16_c(y0, y1, y2, y3,
                          a2[0][0], a2[0][1], a2[0][2], a2[0][3],
                          b2t[0], b2t[1], c2.x, c2.y);
                #pragma unroll
                for (int kt = 1; kt < 4; kt++)
                    mma_f16_acc(y0, y1, y2, y3,
                                a2[kt][0], a2[kt][1], a2[kt][2], a2[kt][3],
                                b2t[2*kt], b2t[2*kt+1]);
                if (tig == 0) {
                    int rowA = tile * 256 + mt * 16 + grp;
                    out2[rowA]     = make_float2(tanh_acc(y0), tanh_acc(y1));
                    out2[rowA + 8] = make_float2(tanh_acc(y2), tanh_acc(y3));
                }
            }
        }
    }
}

extern "C" void kernel_launch(void* const* d_in, const int* in_sizes, int n_in,
                              void* d_out, int out_size)
{
    (void)in_sizes; (void)n_in; (void)out_size;
    const float* X   = (const float*)d_in[0];
    const float* W1  = (const float*)d_in[1];
    const float* b1  = (const float*)d_in[2];
    const float* W2  = (const float*)d_in[3];
    const float* b2  = (const float*)d_in[4];
    const float* W3  = (const float*)d_in[5];
    const float* b3  = (const float*)d_in[6];
    const float* G1  = (const float*)d_in[7];
    const float* gb1 = (const float*)d_in[8];
    const float* G2  = (const float*)d_in[9];
    const float* gb2 = (const float*)d_in[10];
    const float* R1  = (const float*)d_in[11];
    const float* rb1 = (const float*)d_in[12];
    const float* R2  = (const float*)d_in[13];
    const float* rb2 = (const float*)d_in[14];

    cudaFuncSetAttribute(moe_r12_kernel,
                         cudaFuncAttributeMaxDynamicSharedMemorySize, SMEM_TOTAL);

    moe_r12_kernel<<<GRID, 256, SMEM_TOTAL>>>(
        X, W1, b1, W2, b2, W3, b3, G1, gb1, G2, gb2, R1, rb1, R2, rb2,
        (float*)d_out);
}

// round 13
// speedup vs baseline: 1.0218x; 1.0218x over previous
#include <cuda_runtime.h>
#include <cuda_fp16.h>
#include <cstdint>

// Round 13: R11 (147.6us baseline) + ONLY the two verified-safe R12 cuts:
// (a) tanh.approx.f32 for expert outputs, (b) softmax without max-shift.
// NO ldmatrix prefetch (it spilled at the 128-reg cap and regressed R12).
// CTA = 256 threads = 8 warps (warp e = expert e), tile = 256 tokens.

#define NTILES 4096
#define GRID   592

typedef unsigned int u32;

// pack two floats to f16x2: low half = lo, high half = hi
__device__ __forceinline__ u32 f16pk(float lo, float hi) {
    u32 d; asm("cvt.rn.f16x2.f32 %0,%1,%2;" : "=r"(d) : "f"(hi), "f"(lo)); return d;
}
// packed relu: round pair to fp16, then max with +0
__device__ __forceinline__ u32 relu_pk(float lo, float hi) {
    u32 d = f16pk(lo, hi);
    u32 r; asm("max.f16x2 %0,%1,%2;" : "=r"(r) : "r"(d), "r"(0u)); return r;
}
// exact-ish tanh for final output
__device__ __forceinline__ float tanh_acc(float v) {
    float e = __expf(2.0f * v);
    return 1.0f - __fdividef(2.0f, e + 1.0f);
}
// hardware tanh (MUFU.TANH) for intermediate expert outputs
__device__ __forceinline__ float tanh_fast(float v) {
    float r; asm("tanh.approx.f32 %0,%1;" : "=f"(r) : "f"(v)); return r;
}

// ---------------- mma / ldmatrix ----------------
__device__ __forceinline__ void mma_f16_c(float& d0, float& d1, float& d2, float& d3,
                                          u32 a0, u32 a1, u32 a2, u32 a3,
                                          u32 b0, u32 b1, float c0, float c1) {
    asm volatile("mma.sync.aligned.m16n8k16.row.col.f32.f16.f16.f32 "
                 "{%0,%1,%2,%3},{%4,%5,%6,%7},{%8,%9},{%10,%11,%10,%11};"
                 : "=f"(d0), "=f"(d1), "=f"(d2), "=f"(d3)
                 : "r"(a0), "r"(a1), "r"(a2), "r"(a3), "r"(b0), "r"(b1),
                   "f"(c0), "f"(c1));
}
__device__ __forceinline__ void mma_f16_acc(float& d0, float& d1, float& d2, float& d3,
                                            u32 a0, u32 a1, u32 a2, u32 a3,
                                            u32 b0, u32 b1) {
    asm volatile("mma.sync.aligned.m16n8k16.row.col.f32.f16.f16.f32 "
                 "{%0,%1,%2,%3},{%4,%5,%6,%7},{%8,%9},{%0,%1,%2,%3};"
                 : "+f"(d0), "+f"(d1), "+f"(d2), "+f"(d3)
                 : "r"(a0), "r"(a1), "r"(a2), "r"(a3), "r"(b0), "r"(b1));
}
__device__ __forceinline__ void ldm_x4(u32* r, u32 addr) {
    asm volatile("ldmatrix.sync.aligned.m8n8.x4.shared.b16 {%0,%1,%2,%3}, [%4];"
                 : "=r"(r[0]), "=r"(r[1]), "=r"(r[2]), "=r"(r[3]) : "r"(addr));
}
__device__ __forceinline__ u32 smem_to_u32(const void* p) {
    u32 a;
    asm("{ .reg .u64 t; cvta.to.shared.u64 t, %1; cvt.u32.u64 %0, t; }" : "=r"(a) : "l"(p));
    return a;
}

// ---------------- SMEM layout (bytes) ----------------
#define XB  0        // x fp16 rows: 256 x 48B
#define RB  12288    // rin fp16 rows: 256 x 48B
#define WX  24576    // normalized gate weights [8][256] f32   (8 KB)
#define FU  32768    // expert outputs (unweighted tanh) [8][256] float2 (16 KB)
#define TB2 49152    // expert bias2 table [e][nt][tig] float2  (1 KB)
#define GT  50176    // gate lane tables: 32 x 272B
#define RT  58880    // refine lane tables: 32 x 272B
#define SMEM_TOTAL 67584

extern __shared__ char smem_raw[];

__global__ void __launch_bounds__(256, 2)
moe_r13_kernel(const float* __restrict__ X,
               const float* __restrict__ W1, const float* __restrict__ b1,
               const float* __restrict__ W2, const float* __restrict__ b2,
               const float* __restrict__ W3, const float* __restrict__ b3,
               const float* __restrict__ G1, const float* __restrict__ gb1,
               const float* __restrict__ G2, const float* __restrict__ gb2,
               const float* __restrict__ R1, const float* __restrict__ rb1,
               const float* __restrict__ R2, const float* __restrict__ rb2,
               float* __restrict__ out)
{
    const int tid  = threadIdx.x;
    const int wid  = tid >> 5;     // = expert id
    const int lane = tid & 31;
    const int grp  = lane >> 2;
    const int tig  = lane & 3;
    const u32 sbase = smem_to_u32(smem_raw);

    // ---- expert bias2 broadcast table ----
    if (tid < 128) {
        int te = tid >> 4, tn = (tid >> 2) & 3, tg = tid & 3;
        int c0 = tn * 8 + 2 * tg;
        *reinterpret_cast<float2*>(smem_raw + TB2 + tid * 8) =
            make_float2(b2[te * 32 + c0], b2[te * 32 + c0 + 1]);
    }

    // ---- gate / refine per-lane fragment tables (272B stride, conflict-free) ----
    if (tid < 32) {
        int g = tid >> 2, t = tid & 3;
        int k0 = 2 * t;
        {
            char* gt = smem_raw + GT + tid * 272;
            u32*    b1t = reinterpret_cast<u32*>(gt);
            float2* c1t = reinterpret_cast<float2*>(gt + 64);
            u32*    b2t = reinterpret_cast<u32*>(gt + 128);
            float2* c2t = reinterpret_cast<float2*>(gt + 160);
            #pragma unroll
            for (int nt = 0; nt < 8; nt++) {
                int n = nt * 8 + g;
                b1t[nt * 2]     = f16pk(G1[k0 * 64 + n], G1[(k0 + 1) * 64 + n]);
                float wa = (k0 + 8 < 10) ? G1[(k0 + 8) * 64 + n] : 0.f;
                float wb = (k0 + 9 < 10) ? G1[(k0 + 9) * 64 + n] : 0.f;
                b1t[nt * 2 + 1] = f16pk(wa, wb);
                c1t[nt] = make_float2(gb1[nt * 8 + k0], gb1[nt * 8 + k0 + 1]);
            }
            #pragma unroll
            for (int kt = 0; kt < 4; kt++) {
                int kk = kt * 16 + k0;
                b2t[kt * 2]     = f16pk(G2[kk * 8 + g],       G2[(kk + 1) * 8 + g]);
                b2t[kt * 2 + 1] = f16pk(G2[(kk + 8) * 8 + g], G2[(kk + 9) * 8 + g]);
            }
            c2t[0] = make_float2(gb2[k0], gb2[k0 + 1]);
        }
        {
            char* rt = smem_raw + RT + tid * 272;
            u32*    b1t = reinterpret_cast<u32*>(rt);
            float2* c1t = reinterpret_cast<float2*>(rt + 64);
            u32*    b2t = reinterpret_cast<u32*>(rt + 128);
            float2* c2t = reinterpret_cast<float2*>(rt + 160);
            #pragma unroll
            for (int nt = 0; nt < 8; nt++) {
                int n = nt * 8 + g;
                b1t[nt * 2]     = f16pk(R1[k0 * 64 + n], R1[(k0 + 1) * 64 + n]);
                float wa = (k0 + 8 < 12) ? R1[(k0 + 8) * 64 + n] : 0.f;
                float wb = (k0 + 9 < 12) ? R1[(k0 + 9) * 64 + n] : 0.f;
                b1t[nt * 2 + 1] = f16pk(wa, wb);
                c1t[nt] = make_float2(rb1[nt * 8 + k0], rb1[nt * 8 + k0 + 1]);
            }
            #pragma unroll
            for (int kt = 0; kt < 4; kt++) {
                int kk = kt * 16 + k0;
                float wa0 = (g < 2) ? R2[kk * 2 + g] : 0.f;
                float wb0 = (g < 2) ? R2[(kk + 1) * 2 + g] : 0.f;
                b2t[kt * 2]     = f16pk(wa0, wb0);
                float wa1 = (g < 2) ? R2[(kk + 8) * 2 + g] : 0.f;
                float wb1 = (g < 2) ? R2[(kk + 9) * 2 + g] : 0.f;
                b2t[kt * 2 + 1] = f16pk(wa1, wb1);
            }
            c2t[0] = make_float2(t == 0 ? rb2[0] : 0.f, t == 0 ? rb2[1] : 0.f);
        }
    }

    // ---- register-resident fp16 expert fragments (warp e = expert e) ----
    const int e = wid;
    u32 b1f[4][2];            // W1 [nt][b0/b1]
    u32 b2f[4][2][2];         // W2 [nt][kt][b0/b1]
    u32 w3f[2][2];            // W3 [kc][b0/b1], n = grp (zero for grp >= 2)
    float bias1[4][2];
    #pragma unroll
    for (int nt = 0; nt < 4; nt++) {
        int n = nt * 8 + grp;
        b1f[nt][0] = f16pk(W1[e * 320 + (2 * tig) * 32 + n],
                           W1[e * 320 + (2 * tig + 1) * 32 + n]);
        {
            float wa = (2 * tig + 8 < 10) ? W1[e * 320 + (2 * tig + 8) * 32 + n] : 0.f;
            float wb = (2 * tig + 9 < 10) ? W1[e * 320 + (2 * tig + 9) * 32 + n] : 0.f;
            b1f[nt][1] = f16pk(wa, wb);
        }
        #pragma unroll
        for (int kt = 0; kt < 2; kt++) {
            int k0 = kt * 16 + 2 * tig;
            b2f[nt][kt][0] = f16pk(W2[e * 1024 + k0 * 32 + n],
                                   W2[e * 1024 + (k0 + 1) * 32 + n]);
            b2f[nt][kt][1] = f16pk(W2[e * 1024 + (k0 + 8) * 32 + n],
                                   W2[e * 1024 + (k0 + 9) * 32 + n]);
        }
        int c0 = nt * 8 + 2 * tig;
        bias1[nt][0] = b1[e * 32 + c0];
        bias1[nt][1] = b1[e * 32 + c0 + 1];
    }
    #pragma unroll
    for (int kc = 0; kc < 2; kc++) {
        int kb = kc * 16;
        float v00 = (grp < 2) ? W3[e * 64 + (kb + 2 * tig) * 2 + grp] : 0.f;
        float v01 = (grp < 2) ? W3[e * 64 + (kb + 2 * tig + 1) * 2 + grp] : 0.f;
        w3f[kc][0] = f16pk(v00, v01);
        float v10 = (grp < 2) ? W3[e * 64 + (kb + 8 + 2 * tig) * 2 + grp] : 0.f;
        float v11 = (grp < 2) ? W3[e * 64 + (kb + 9 + 2 * tig) * 2 + grp] : 0.f;
        w3f[kc][1] = f16pk(v10, v11);
    }
    const float b3e0 = b3[e * 2], b3e1 = b3[e * 2 + 1];
    __syncthreads();

    for (int tile = blockIdx.x; tile < NTILES; tile += gridDim.x) {
        const int tok = tile * 256 + tid;

        // ============ phase 1: load x, stage fp16 rows ============
        u32 xs[5];
        {
            const float2* xp = reinterpret_cast<const float2*>(X + (size_t)tok * 10);
            #pragma unroll
            for (int i = 0; i < 5; i++) {
                float2 v = xp[i];
                xs[i] = f16pk(v.x, v.y);
            }
            uint4* p = reinterpret_cast<uint4*>(smem_raw + XB + tid * 48);
            p[0] = make_uint4(xs[0], xs[1], xs[2], xs[3]);
            p[1] = make_uint4(xs[4], 0u, 0u, 0u);
        }
        __syncthreads();

        // ============ phase 2a: gate via mma (2 m-tiles per warp) ============
        {
            const char* gt = smem_raw + GT + (u32)lane * 272;
            const u32*    b1t = reinterpret_cast<const u32*>(gt);
            const float2* c1t = reinterpret_cast<const float2*>(gt + 64);
            const u32*    b2t = reinterpret_cast<const u32*>(gt + 128);
            const float2  c2  = *reinterpret_cast<const float2*>(gt + 160);
            float* wxp = reinterpret_cast<float*>(smem_raw + WX);
            #pragma unroll 1
            for (int q = 0; q < 2; q++) {
                int mt = wid * 2 + q;
                u32 ax[4];
                ldm_x4(ax, sbase + XB + (u32)(mt * 16 + (lane & 15)) * 48
                           + ((lane >> 4) << 4));
                float d[8][4];
                #pragma unroll
                for (int nt = 0; nt < 8; nt++) {
                    float2 cc = c1t[nt];
                    mma_f16_c(d[nt][0], d[nt][1], d[nt][2], d[nt][3],
                              ax[0], ax[1], ax[2], ax[3],
                              b1t[2*nt], b1t[2*nt+1], cc.x, cc.y);
                }
                u32 a2[4][4];
                #pragma unroll
                for (int kt = 0; kt < 4; kt++) {
                    a2[kt][0] = relu_pk(d[2*kt][0],   d[2*kt][1]);
                    a2[kt][1] = relu_pk(d[2*kt][2],   d[2*kt][3]);
                    a2[kt][2] = relu_pk(d[2*kt+1][0], d[2*kt+1][1]);
                    a2[kt][3] = relu_pk(d[2*kt+1][2], d[2*kt+1][3]);
                }
                float l0, l1, l2, l3;
                mma_f16_c(l0, l1, l2, l3,
                          a2[0][0], a2[0][1], a2[0][2], a2[0][3],
                          b2t[0], b2t[1], c2.x, c2.y);
                #pragma unroll
                for (int kt = 1; kt < 4; kt++)
                    mma_f16_acc(l0, l1, l2, l3,
                                a2[kt][0], a2[kt][1], a2[kt][2], a2[kt][3],
                                b2t[2*kt], b2t[2*kt+1]);
                // softmax per row (logits bounded: no max-shift needed)
                float eA0 = __expf(l0), eA1 = __expf(l1);
                float sA = eA0 + eA1;
                sA += __shfl_xor_sync(0xFFFFFFFFu, sA, 1);
                sA += __shfl_xor_sync(0xFFFFFFFFu, sA, 2);
                float iA = __fdividef(1.f, sA);
                float eB0 = __expf(l2), eB1 = __expf(l3);
                float sB = eB0 + eB1;
                sB += __shfl_xor_sync(0xFFFFFFFFu, sB, 1);
                sB += __shfl_xor_sync(0xFFFFFFFFu, sB, 2);
                float iB = __fdividef(1.f, sB);
                int rowA = mt * 16 + grp;
                wxp[(2*tig)   * 256 + rowA]     = eA0 * iA;
                wxp[(2*tig+1) * 256 + rowA]     = eA1 * iA;
                wxp[(2*tig)   * 256 + rowA + 8] = eB0 * iB;
                wxp[(2*tig+1) * 256 + rowA + 8] = eB1 * iB;
            }
        }

        // ============ phase 2b: expert GEMMs (warp = expert, 16 m-tiles) ============
        {
            float2* fup = reinterpret_cast<float2*>(smem_raw + FU);
            #pragma unroll 1
            for (int mt = 0; mt < 16; mt++) {
                u32 ax[4];
                ldm_x4(ax, sbase + XB + (u32)(mt * 16 + (lane & 15)) * 48
                           + ((lane >> 4) << 4));
                // L1 (bias in C)
                float d[4][4];
                #pragma unroll
                for (int nt = 0; nt < 4; nt++)
                    mma_f16_c(d[nt][0], d[nt][1], d[nt][2], d[nt][3],
                              ax[0], ax[1], ax[2], ax[3],
                              b1f[nt][0], b1f[nt][1], bias1[nt][0], bias1[nt][1]);
                // packed relu -> L2 A-frags
                u32 a2[2][4];
                #pragma unroll
                for (int nt = 0; nt < 4; nt++) {
                    int kt = nt >> 1, hf = (nt & 1) << 1;
                    a2[kt][hf]     = relu_pk(d[nt][0], d[nt][1]);
                    a2[kt][hf + 1] = relu_pk(d[nt][2], d[nt][3]);
                }
                // L2 (bias2 from table via C)
                float g[4][4];
                #pragma unroll
                for (int nt = 0; nt < 4; nt++) {
                    float2 tb = *reinterpret_cast<const float2*>(
                        smem_raw + TB2 + (u32)(((e * 4 + nt) * 4 + tig)) * 8);
                    mma_f16_c(g[nt][0], g[nt][1], g[nt][2], g[nt][3],
                              a2[0][0], a2[0][1], a2[0][2], a2[0][3],
                              b2f[nt][0][0], b2f[nt][0][1], tb.x, tb.y);
                    mma_f16_acc(g[nt][0], g[nt][1], g[nt][2], g[nt][3],
                                a2[1][0], a2[1][1], a2[1][2], a2[1][3],
                                b2f[nt][1][0], b2f[nt][1][1]);
                }
                // packed relu -> L3 A-frags
                u32 p3[4][2];
                #pragma unroll
                for (int nt = 0; nt < 4; nt++) {
                    p3[nt][0] = relu_pk(g[nt][0], g[nt][1]);
                    p3[nt][1] = relu_pk(g[nt][2], g[nt][3]);
                }
                // L3 via mma pair (bias3 in C); valid cols 0,1 land on tig==0
                float y0, y1, y2, y3;
                mma_f16_c(y0, y1, y2, y3,
                          p3[0][0], p3[0][1], p3[1][0], p3[1][1],
                          w3f[0][0], w3f[0][1], b3e0, b3e1);
                mma_f16_acc(y0, y1, y2, y3,
                            p3[2][0], p3[2][1], p3[3][0], p3[3][1],
                            w3f[1][0], w3f[1][1]);
                if (tig == 0) {
                    int tk = mt * 16 + grp;
                    fup[e * 256 + tk]     = make_float2(tanh_fast(y0), tanh_fast(y1));
                    fup[e * 256 + tk + 8] = make_float2(tanh_fast(y2), tanh_fast(y3));
                }
            }
        }
        __syncthreads();

        // ============ phase 3: fuse + restage rin ============
        {
            const float2* fup = reinterpret_cast<const float2*>(smem_raw + FU);
            const float* wxp = reinterpret_cast<const float*>(smem_raw + WX);
            float f0 = 0.f, f1 = 0.f;
            #pragma unroll
            for (int q2 = 0; q2 < 8; q2++) {
                float2 s = fup[q2 * 256 + tid];
                float w = wxp[q2 * 256 + tid];
                f0 += w * s.x; f1 += w * s.y;
            }
            uint4* p = reinterpret_cast<uint4*>(smem_raw + RB + tid * 48);
            p[0] = make_uint4(f16pk(f0, f1), xs[0], xs[1], xs[2]);
            p[1] = make_uint4(xs[3], xs[4], 0u, 0u);
        }
        __syncthreads();

        // ============ phase 4: refine via mma (2 m-tiles per warp) ============
        {
            const char* rt = smem_raw + RT + (u32)lane * 272;
            const u32*    b1t = reinterpret_cast<const u32*>(rt);
            const float2* c1t = reinterpret_cast<const float2*>(rt + 64);
            const u32*    b2t = reinterpret_cast<const u32*>(rt + 128);
            const float2  c2  = *reinterpret_cast<const float2*>(rt + 160);
            float2* out2 = reinterpret_cast<float2*>(out);
            #pragma unroll 1
            for (int q = 0; q < 2; q++) {
                int mt = wid * 2 + q;
                u32 ax[4];
                ldm_x4(ax, sbase + RB + (u32)(mt * 16 + (lane & 15)) * 48
                           + ((lane >> 4) << 4));
                float d[8][4];
                #pragma unroll
                for (int nt = 0; nt < 8; nt++) {
                    float2 cc = c1t[nt];
                    mma_f16_c(d[nt][0], d[nt][1], d[nt][2], d[nt][3],
                              ax[0], ax[1], ax[2], ax[3],
                              b1t[2*nt], b1t[2*nt+1], cc.x, cc.y);
                }
                u32 a2[4][4];
                #pragma unroll
                for (int kt = 0; kt < 4; kt++) {
                    a2[kt][0] = relu_pk(d[2*kt][0],   d[2*kt][1]);
                    a2[kt][1] = relu_pk(d[2*kt][2],   d[2*kt][3]);
                    a2[kt][2] = relu_pk(d[2*kt+1][0], d[2*kt+1][1]);
                    a2[kt][3] = relu_pk(d[2*kt+1][2], d[2*kt+1][3]);
                }
                float y0, y1, y2, y3;
                mma_f16_c(y0, y1, y2, y3,
                          a2[0][0], a2[0][1], a2[0][2], a2[0][3],
                          b2t[0], b2t[1], c2.x, c2.y);
                #pragma unroll
                for (int kt = 1; kt < 4; kt++)
                    mma_f16_acc(y0, y1, y2, y3,
                                a2[kt][0], a2[kt][1], a2[kt][2], a2[kt][3],
                                b2t[2*kt], b2t[2*kt+1]);
                if (tig == 0) {
                    int rowA = tile * 256 + mt * 16 + grp;
                    out2[rowA]     = make_float2(tanh_acc(y0), tanh_acc(y1));
                    out2[rowA + 8] = make_float2(tanh_acc(y2), tanh_acc(y3));
                }
            }
        }
    }
}

extern "C" void kernel_launch(void* const* d_in, const int* in_sizes, int n_in,
                              void* d_out, int out_size)
{
    (void)in_sizes; (void)n_in; (void)out_size;
    const float* X   = (const float*)d_in[0];
    const float* W1  = (const float*)d_in[1];
    const float* b1  = (const float*)d_in[2];
    const float* W2  = (const float*)d_in[3];
    const float* b2  = (const float*)d_in[4];
    const float* W3  = (const float*)d_in[5];
    const float* b3  = (const float*)d_in[6];
    const float* G1  = (const float*)d_in[7];
    const float* gb1 = (const float*)d_in[8];
    const float* G2  = (const float*)d_in[9];
    const float* gb2 = (const float*)d_in[10];
    const float* R1  = (const float*)d_in[11];
    const float* rb1 = (const float*)d_in[12];
    const float* R2  = (const float*)d_in[13];
    const float* rb2 = (const float*)d_in[14];

    cudaFuncSetAttribute(moe_r13_kernel,
                         cudaFuncAttributeMaxDynamicSharedMemorySize, SMEM_TOTAL);

    moe_r13_kernel<<<GRID, 256, SMEM_TOTAL>>>(
        X, W1, b1, W2, b2, W3, b3, G1, gb1, G2, gb2, R1, rb1, R2, rb2,
        (float*)d_out);
}

// round 14
// speedup vs baseline: 1.4274x; 1.3969x over previous
#include <cuda_runtime.h>
#include <cuda_fp16.h>
#include <cstdint>

// Round 14: exact R11 baseline (147.6us: tanh_acc everywhere, max-shift
// softmax, no prefetch) + ONE change: expert L1 uses f16-output mma
// (D packed f16x2 == next A-fragment layout; relu = max.f16x2, zero cvt).
// CTA = 256 threads = 8 warps (warp e = expert e), tile = 256 tokens.

#define NTILES 4096
#define GRID   592

typedef unsigned int u32;

// pack two floats to f16x2: low half = lo, high half = hi
__device__ __forceinline__ u32 f16pk(float lo, float hi) {
    u32 d; asm("cvt.rn.f16x2.f32 %0,%1,%2;" : "=r"(d) : "f"(hi), "f"(lo)); return d;
}
// packed relu from two f32
__device__ __forceinline__ u32 relu_pk(float lo, float hi) {
    u32 d = f16pk(lo, hi);
    u32 r; asm("max.f16x2 %0,%1,%2;" : "=r"(r) : "r"(d), "r"(0u)); return r;
}
// packed relu on an already-packed f16x2
__device__ __forceinline__ u32 max0_pk(u32 v) {
    u32 r; asm("max.f16x2 %0,%1,%2;" : "=r"(r) : "r"(v), "r"(0u)); return r;
}
// accurate tanh (exact identity + fast exp)
__device__ __forceinline__ float tanh_acc(float v) {
    float e = __expf(2.0f * v);
    return 1.0f - __fdividef(2.0f, e + 1.0f);
}

// ---------------- mma / ldmatrix ----------------
// f32-accum variants
__device__ __forceinline__ void mma_f16_c(float& d0, float& d1, float& d2, float& d3,
                                          u32 a0, u32 a1, u32 a2, u32 a3,
                                          u32 b0, u32 b1, float c0, float c1) {
    asm volatile("mma.sync.aligned.m16n8k16.row.col.f32.f16.f16.f32 "
                 "{%0,%1,%2,%3},{%4,%5,%6,%7},{%8,%9},{%10,%11,%10,%11};"
                 : "=f"(d0), "=f"(d1), "=f"(d2), "=f"(d3)
                 : "r"(a0), "r"(a1), "r"(a2), "r"(a3), "r"(b0), "r"(b1),
                   "f"(c0), "f"(c1));
}
__device__ __forceinline__ void mma_f16_acc(float& d0, float& d1, float& d2, float& d3,
                                            u32 a0, u32 a1, u32 a2, u32 a3,
                                            u32 b0, u32 b1) {
    asm volatile("mma.sync.aligned.m16n8k16.row.col.f32.f16.f16.f32 "
                 "{%0,%1,%2,%3},{%4,%5,%6,%7},{%8,%9},{%0,%1,%2,%3};"
                 : "+f"(d0), "+f"(d1), "+f"(d2), "+f"(d3)
                 : "r"(a0), "r"(a1), "r"(a2), "r"(a3), "r"(b0), "r"(b1));
}
// f16-out variant: D,C packed f16x2; C = {bp, bp} (same bias pair both rows)
__device__ __forceinline__ void mma_h16_c(u32& d0, u32& d1,
                                          u32 a0, u32 a1, u32 a2, u32 a3,
                                          u32 b0, u32 b1, u32 bp) {
    asm volatile("mma.sync.aligned.m16n8k16.row.col.f16.f16.f16.f16 "
                 "{%0,%1},{%2,%3,%4,%5},{%6,%7},{%8,%8};"
                 : "=r"(d0), "=r"(d1)
                 : "r"(a0), "r"(a1), "r"(a2), "r"(a3), "r"(b0), "r"(b1), "r"(bp));
}
__device__ __forceinline__ void ldm_x4(u32* r, u32 addr) {
    asm volatile("ldmatrix.sync.aligned.m8n8.x4.shared.b16 {%0,%1,%2,%3}, [%4];"
                 : "=r"(r[0]), "=r"(r[1]), "=r"(r[2]), "=r"(r[3]) : "r"(addr));
}
__device__ __forceinline__ u32 smem_to_u32(const void* p) {
    u32 a;
    asm("{ .reg .u64 t; cvta.to.shared.u64 t, %1; cvt.u32.u64 %0, t; }" : "=r"(a) : "l"(p));
    return a;
}

// ---------------- SMEM layout (bytes) ----------------
#define XB  0        // x fp16 rows: 256 x 48B
#define RB  12288    // rin fp16 rows: 256 x 48B
#define WX  24576    // normalized gate weights [8][256] f32   (8 KB)
#define FU  32768    // expert outputs (unweighted tanh) [8][256] float2 (16 KB)
#define TB2 49152    // expert bias2 table [e][nt][tig] float2  (1 KB)
#define GT  50176    // gate lane tables: 32 x 272B
#define RT  58880    // refine lane tables: 32 x 272B
#define SMEM_TOTAL 67584

extern __shared__ char smem_raw[];

__global__ void __launch_bounds__(256, 2)
moe_r14_kernel(const float* __restrict__ X,
               const float* __restrict__ W1, const float* __restrict__ b1,
               const float* __restrict__ W2, const float* __restrict__ b2,
               const float* __restrict__ W3, const float* __restrict__ b3,
               const float* __restrict__ G1, const float* __restrict__ gb1,
               const float* __restrict__ G2, const float* __restrict__ gb2,
               const float* __restrict__ R1, const float* __restrict__ rb1,
               const float* __restrict__ R2, const float* __restrict__ rb2,
               float* __restrict__ out)
{
    const int tid  = threadIdx.x;
    const int wid  = tid >> 5;     // = expert id
    const int lane = tid & 31;
    const int grp  = lane >> 2;
    const int tig  = lane & 3;
    const u32 sbase = smem_to_u32(smem_raw);

    // ---- expert bias2 broadcast table ----
    if (tid < 128) {
        int te = tid >> 4, tn = (tid >> 2) & 3, tg = tid & 3;
        int c0 = tn * 8 + 2 * tg;
        *reinterpret_cast<float2*>(smem_raw + TB2 + tid * 8) =
            make_float2(b2[te * 32 + c0], b2[te * 32 + c0 + 1]);
    }

    // ---- gate / refine per-lane fragment tables (272B stride, conflict-free) ----
    if (tid < 32) {
        int g = tid >> 2, t = tid & 3;
        int k0 = 2 * t;
        {
            char* gt = smem_raw + GT + tid * 272;
            u32*    b1t = reinterpret_cast<u32*>(gt);
            float2* c1t = reinterpret_cast<float2*>(gt + 64);
            u32*    b2t = reinterpret_cast<u32*>(gt + 128);
            float2* c2t = reinterpret_cast<float2*>(gt + 160);
            #pragma unroll
            for (int nt = 0; nt < 8; nt++) {
                int n = nt * 8 + g;
                b1t[nt * 2]     = f16pk(G1[k0 * 64 + n], G1[(k0 + 1) * 64 + n]);
                float wa = (k0 + 8 < 10) ? G1[(k0 + 8) * 64 + n] : 0.f;
                float wb = (k0 + 9 < 10) ? G1[(k0 + 9) * 64 + n] : 0.f;
                b1t[nt * 2 + 1] = f16pk(wa, wb);
                c1t[nt] = make_float2(gb1[nt * 8 + k0], gb1[nt * 8 + k0 + 1]);
            }
            #pragma unroll
            for (int kt = 0; kt < 4; kt++) {
                int kk = kt * 16 + k0;
                b2t[kt * 2]     = f16pk(G2[kk * 8 + g],       G2[(kk + 1) * 8 + g]);
                b2t[kt * 2 + 1] = f16pk(G2[(kk + 8) * 8 + g], G2[(kk + 9) * 8 + g]);
            }
            c2t[0] = make_float2(gb2[k0], gb2[k0 + 1]);
        }
        {
            char* rt = smem_raw + RT + tid * 272;
            u32*    b1t = reinterpret_cast<u32*>(rt);
            float2* c1t = reinterpret_cast<float2*>(rt + 64);
            u32*    b2t = reinterpret_cast<u32*>(rt + 128);
            float2* c2t = reinterpret_cast<float2*>(rt + 160);
            #pragma unroll
            for (int nt = 0; nt < 8; nt++) {
                int n = nt * 8 + g;
                b1t[nt * 2]     = f16pk(R1[k0 * 64 + n], R1[(k0 + 1) * 64 + n]);
                float wa = (k0 + 8 < 12) ? R1[(k0 + 8) * 64 + n] : 0.f;
                float wb = (k0 + 9 < 12) ? R1[(k0 + 9) * 64 + n] : 0.f;
                b1t[nt * 2 + 1] = f16pk(wa, wb);
                c1t[nt] = make_float2(rb1[nt * 8 + k0], rb1[nt * 8 + k0 + 1]);
            }
            #pragma unroll
            for (int kt = 0; kt < 4; kt++) {
                int kk = kt * 16 + k0;
                float wa0 = (g < 2) ? R2[kk * 2 + g] : 0.f;
                float wb0 = (g < 2) ? R2[(kk + 1) * 2 + g] : 0.f;
                b2t[kt * 2]     = f16pk(wa0, wb0);
                float wa1 = (g < 2) ? R2[(kk + 8) * 2 + g] : 0.f;
                float wb1 = (g < 2) ? R2[(kk + 9) * 2 + g] : 0.f;
                b2t[kt * 2 + 1] = f16pk(wa1, wb1);
            }
            c2t[0] = make_float2(t == 0 ? rb2[0] : 0.f, t == 0 ? rb2[1] : 0.f);
        }
    }

    // ---- register-resident fp16 expert fragments (warp e = expert e) ----
    const int e = wid;
    u32 b1f[4][2];            // W1 [nt][b0/b1]
    u32 b2f[4][2][2];         // W2 [nt][kt][b0/b1]
    u32 w3f[2][2];            // W3 [kc][b0/b1], n = grp (zero for grp >= 2)
    u32 bias1p[4];            // packed f16x2 bias pairs for L1 (f16-D mma C)
    #pragma unroll
    for (int nt = 0; nt < 4; nt++) {
        int n = nt * 8 + grp;
        b1f[nt][0] = f16pk(W1[e * 320 + (2 * tig) * 32 + n],
                           W1[e * 320 + (2 * tig + 1) * 32 + n]);
        {
            float wa = (2 * tig + 8 < 10) ? W1[e * 320 + (2 * tig + 8) * 32 + n] : 0.f;
            float wb = (2 * tig + 9 < 10) ? W1[e * 320 + (2 * tig + 9) * 32 + n] : 0.f;
            b1f[nt][1] = f16pk(wa, wb);
        }
        #pragma unroll
        for (int kt = 0; kt < 2; kt++) {
            int k0 = kt * 16 + 2 * tig;
            b2f[nt][kt][0] = f16pk(W2[e * 1024 + k0 * 32 + n],
                                   W2[e * 1024 + (k0 + 1) * 32 + n]);
            b2f[nt][kt][1] = f16pk(W2[e * 1024 + (k0 + 8) * 32 + n],
                                   W2[e * 1024 + (k0 + 9) * 32 + n]);
        }
        int c0 = nt * 8 + 2 * tig;
        bias1p[nt] = f16pk(b1[e * 32 + c0], b1[e * 32 + c0 + 1]);
    }
    #pragma unroll
    for (int kc = 0; kc < 2; kc++) {
        int kb = kc * 16;
        float v00 = (grp < 2) ? W3[e * 64 + (kb + 2 * tig) * 2 + grp] : 0.f;
        float v01 = (grp < 2) ? W3[e * 64 + (kb + 2 * tig + 1) * 2 + grp] : 0.f;
        w3f[kc][0] = f16pk(v00, v01);
        float v10 = (grp < 2) ? W3[e * 64 + (kb + 8 + 2 * tig) * 2 + grp] : 0.f;
        float v11 = (grp < 2) ? W3[e * 64 + (kb + 9 + 2 * tig) * 2 + grp] : 0.f;
        w3f[kc][1] = f16pk(v10, v11);
    }
    const float b3e0 = b3[e * 2], b3e1 = b3[e * 2 + 1];
    __syncthreads();

    for (int tile = blockIdx.x; tile < NTILES; tile += gridDim.x) {
        const int tok = tile * 256 + tid;

        // ============ phase 1: load x, stage fp16 rows ============
        u32 xs[5];
        {
            const float2* xp = reinterpret_cast<const float2*>(X + (size_t)tok * 10);
            #pragma unroll
            for (int i = 0; i < 5; i++) {
                float2 v = xp[i];
                xs[i] = f16pk(v.x, v.y);
            }
            uint4* p = reinterpret_cast<uint4*>(smem_raw + XB + tid * 48);
            p[0] = make_uint4(xs[0], xs[1], xs[2], xs[3]);
            p[1] = make_uint4(xs[4], 0u, 0u, 0u);
        }
        __syncthreads();

        // ============ phase 2a: gate via mma (2 m-tiles per warp) ============
        {
            const char* gt = smem_raw + GT + (u32)lane * 272;
            const u32*    b1t = reinterpret_cast<const u32*>(gt);
            const float2* c1t = reinterpret_cast<const float2*>(gt + 64);
            const u32*    b2t = reinterpret_cast<const u32*>(gt + 128);
            const float2  c2  = *reinterpret_cast<const float2*>(gt + 160);
            float* wxp = reinterpret_cast<float*>(smem_raw + WX);
            #pragma unroll 1
            for (int q = 0; q < 2; q++) {
                int mt = wid * 2 + q;
                u32 ax[4];
                ldm_x4(ax, sbase + XB + (u32)(mt * 16 + (lane & 15)) * 48
                           + ((lane >> 4) << 4));
                float d[8][4];
                #pragma unroll
                for (int nt = 0; nt < 8; nt++) {
                    float2 cc = c1t[nt];
                    mma_f16_c(d[nt][0], d[nt][1], d[nt][2], d[nt][3],
                              ax[0], ax[1], ax[2], ax[3],
                              b1t[2*nt], b1t[2*nt+1], cc.x, cc.y);
                }
                u32 a2[4][4];
                #pragma unroll
                for (int kt = 0; kt < 4; kt++) {
                    a2[kt][0] = relu_pk(d[2*kt][0],   d[2*kt][1]);
                    a2[kt][1] = relu_pk(d[2*kt][2],   d[2*kt][3]);
                    a2[kt][2] = relu_pk(d[2*kt+1][0], d[2*kt+1][1]);
                    a2[kt][3] = relu_pk(d[2*kt+1][2], d[2*kt+1][3]);
                }
                float l0, l1, l2, l3;
                mma_f16_c(l0, l1, l2, l3,
                          a2[0][0], a2[0][1], a2[0][2], a2[0][3],
                          b2t[0], b2t[1], c2.x, c2.y);
                #pragma unroll
                for (int kt = 1; kt < 4; kt++)
                    mma_f16_acc(l0, l1, l2, l3,
                                a2[kt][0], a2[kt][1], a2[kt][2], a2[kt][3],
                                b2t[2*kt], b2t[2*kt+1]);
                // softmax per row (8 logits spread over quad, 2 per lane)
                float mA = fmaxf(l0, l1);
                mA = fmaxf(mA, __shfl_xor_sync(0xFFFFFFFFu, mA, 1));
                mA = fmaxf(mA, __shfl_xor_sync(0xFFFFFFFFu, mA, 2));
                float eA0 = __expf(l0 - mA), eA1 = __expf(l1 - mA);
                float sA = eA0 + eA1;
                sA += __shfl_xor_sync(0xFFFFFFFFu, sA, 1);
                sA += __shfl_xor_sync(0xFFFFFFFFu, sA, 2);
                float iA = __fdividef(1.f, sA);
                float mB = fmaxf(l2, l3);
                mB = fmaxf(mB, __shfl_xor_sync(0xFFFFFFFFu, mB, 1));
                mB = fmaxf(mB, __shfl_xor_sync(0xFFFFFFFFu, mB, 2));
                float eB0 = __expf(l2 - mB), eB1 = __expf(l3 - mB);
                float sB = eB0 + eB1;
                sB += __shfl_xor_sync(0xFFFFFFFFu, sB, 1);
                sB += __shfl_xor_sync(0xFFFFFFFFu, sB, 2);
                float iB = __fdividef(1.f, sB);
                int rowA = mt * 16 + grp;
                wxp[(2*tig)   * 256 + rowA]     = eA0 * iA;
                wxp[(2*tig+1) * 256 + rowA]     = eA1 * iA;
                wxp[(2*tig)   * 256 + rowA + 8] = eB0 * iB;
                wxp[(2*tig+1) * 256 + rowA + 8] = eB1 * iB;
            }
        }

        // ============ phase 2b: expert GEMMs (warp = expert, 16 m-tiles) ============
        {
            float2* fup = reinterpret_cast<float2*>(smem_raw + FU);
            #pragma unroll 1
            for (int mt = 0; mt < 16; mt++) {
                u32 ax[4];
                ldm_x4(ax, sbase + XB + (u32)(mt * 16 + (lane & 15)) * 48
                           + ((lane >> 4) << 4));
                // L1 (f16-D mma, bias via packed C); relu = max.f16x2, no cvt.
                // dh[nt][0] = rows grp, cols pair; dh[nt][1] = rows grp+8.
                u32 a2[2][4];
                #pragma unroll
                for (int nt = 0; nt < 4; nt++) {
                    u32 dh0, dh1;
                    mma_h16_c(dh0, dh1, ax[0], ax[1], ax[2], ax[3],
                              b1f[nt][0], b1f[nt][1], bias1p[nt]);
                    int kt = nt >> 1, hf = (nt & 1) << 1;
                    a2[kt][hf]     = max0_pk(dh0);
                    a2[kt][hf + 1] = max0_pk(dh1);
                }
                // L2 (f32 accum, bias2 from table via C)
                float g[4][4];
                #pragma unroll
                for (int nt = 0; nt < 4; nt++) {
                    float2 tb = *reinterpret_cast<const float2*>(
                        smem_raw + TB2 + (u32)(((e * 4 + nt) * 4 + tig)) * 8);
                    mma_f16_c(g[nt][0], g[nt][1], g[nt][2], g[nt][3],
                              a2[0][0], a2[0][1], a2[0][2], a2[0][3],
                              b2f[nt][0][0], b2f[nt][0][1], tb.x, tb.y);
                    mma_f16_acc(g[nt][0], g[nt][1], g[nt][2], g[nt][3],
                                a2[1][0], a2[1][1], a2[1][2], a2[1][3],
                                b2f[nt][1][0], b2f[nt][1][1]);
                }
                // packed relu -> L3 A-frags
                u32 p3[4][2];
                #pragma unroll
                for (int nt = 0; nt < 4; nt++) {
                    p3[nt][0] = relu_pk(g[nt][0], g[nt][1]);
                    p3[nt][1] = relu_pk(g[nt][2], g[nt][3]);
                }
                // L3 via mma pair (bias3 in C); valid cols 0,1 land on tig==0
                float y0, y1, y2, y3;
                mma_f16_c(y0, y1, y2, y3,
                          p3[0][0], p3[0][1], p3[1][0], p3[1][1],
                          w3f[0][0], w3f[0][1], b3e0, b3e1);
                mma_f16_acc(y0, y1, y2, y3,
                            p3[2][0], p3[2][1], p3[3][0], p3[3][1],
                            w3f[1][0], w3f[1][1]);
                if (tig == 0) {
                    int tk = mt * 16 + grp;
                    fup[e * 256 + tk]     = make_float2(tanh_acc(y0), tanh_acc(y1));
                    fup[e * 256 + tk + 8] = make_float2(tanh_acc(y2), tanh_acc(y3));
                }
            }
        }
        __syncthreads();

        // ============ phase 3: fuse + restage rin ============
        {
            const float2* fup = reinterpret_cast<const float2*>(smem_raw + FU);
            const float* wxp = reinterpret_cast<const float*>(smem_raw + WX);
            float f0 = 0.f, f1 = 0.f;
            #pragma unroll
            for (int q2 = 0; q2 < 8; q2++) {
                float2 s = fup[q2 * 256 + tid];
                float w = wxp[q2 * 256 + tid];
                f0 += w * s.x; f1 += w * s.y;
            }
            uint4* p = reinterpret_cast<uint4*>(smem_raw + RB + tid * 48);
            p[0] = make_uint4(f16pk(f0, f1), xs[0], xs[1], xs[2]);
            p[1] = make_uint4(xs[3], xs[4], 0u, 0u);
        }
        __syncthreads();

        // ============ phase 4: refine via mma (2 m-tiles per warp) ============
        {
            const char* rt = smem_raw + RT + (u32)lane * 272;
            const u32*    b1t = reinterpret_cast<const u32*>(rt);
            const float2* c1t = reinterpret_cast<const float2*>(rt + 64);
            const u32*    b2t = reinterpret_cast<const u32*>(rt + 128);
            const float2  c2  = *reinterpret_cast<const float2*>(rt + 160);
            float2* out2 = reinterpret_cast<float2*>(out);
            #pragma unroll 1
            for (int q = 0; q < 2; q++) {
                int mt = wid * 2 + q;
                u32 ax[4];
                ldm_x4(ax, sbase + RB + (u32)(mt * 16 + (lane & 15)) * 48
                           + ((lane >> 4) << 4));
                float d[8][4];
                #pragma unroll
                for (int nt = 0; nt < 8; nt++) {
                    float2 cc = c1t[nt];
                    mma_f16_c(d[nt][0], d[nt][1], d[nt][2], d[nt][3],
                              ax[0], ax[1], ax[2], ax[3],
                              b1t[2*nt], b1t[2*nt+1], cc.x, cc.y);
                }
                u32 a2[4][4];
                #pragma unroll
                for (int kt = 0; kt < 4; kt++) {
                    a2[kt][0] = relu_pk(d[2*kt][0],   d[2*kt][1]);
                    a2[kt][1] = relu_pk(d[2*kt][2],   d[2*kt][3]);
                    a2[kt][2] = relu_pk(d[2*kt+1][0], d[2*kt+1][1]);
                    a2[kt][3] = relu_pk(d[2*kt+1][2], d[2*kt+1][3]);
                }
                float y0, y1, y2, y3;
                mma_f16_c(y0, y1, y2, y3,
                          a2[0][0], a2[0][1], a2[0][2], a2[0][3],
                          b2t[0], b2t[1], c2.x, c2.y);
                #pragma unroll
                for (int kt = 1; kt < 4; kt++)
                    mma_f16_acc(y0, y1, y2, y3,
                                a2[kt][0], a2[kt][1], a2[kt][2], a2[kt][3],
                                b2t[2*kt], b2t[2*kt+1]);
                if (tig == 0) {
                    int rowA = tile * 256 + mt * 16 + grp;
                    out2[rowA]     = make_float2(tanh_acc(y0), tanh_acc(y1));
                    out2[rowA + 8] = make_float2(tanh_acc(y2), tanh_acc(y3));
                }
            }
        }
    }
}

extern "C" void kernel_launch(void* const* d_in, const int* in_sizes, int n_in,
                              void* d_out, int out_size)
{
    (void)in_sizes; (void)n_in; (void)out_size;
    const float* X   = (const float*)d_in[0];
    const float* W1  = (const float*)d_in[1];
    const float* b1  = (const float*)d_in[2];
    const float* W2  = (const float*)d_in[3];
    const float* b2  = (const float*)d_in[4];
    const float* W3  = (const float*)d_in[5];
    const float* b3  = (const float*)d_in[6];
    const float* G1  = (const float*)d_in[7];
    const float* gb1 = (const float*)d_in[8];
    const float* G2  = (const float*)d_in[9];
    const float* gb2 = (const float*)d_in[10];
    const float* R1  = (const float*)d_in[11];
    const float* rb1 = (const float*)d_in[12];
    const float* R2  = (const float*)d_in[13];
    const float* rb2 = (const float*)d_in[14];

    cudaFuncSetAttribute(moe_r14_kernel,
                         cudaFuncAttributeMaxDynamicSharedMemorySize, SMEM_TOTAL);

    moe_r14_kernel<<<GRID, 256, SMEM_TOTAL>>>(
        X, W1, b1, W2, b2, W3, b3, G1, gb1, G2, gb2, R1, rb1, R2, rb2,
        (float*)d_out);
}

// round 15
// speedup vs baseline: 1.5690x; 1.0992x over previous
#include <cuda_runtime.h>
#include <cuda_fp16.h>
#include <cstdint>

// Round 15: R14 (139.7us) + f16-output mma for ALL relu epilogues
// (expert L1+L2, gate L1, refine L1): D-frag == next A-frag, relu = max.f16x2,
// zero cvt. Final-output mmas (gate logits, expert L3, refine L2) stay f32.
// CTA = 256 threads = 8 warps (warp e = expert e), tile = 256 tokens.

#define NTILES 4096
#define GRID   592

typedef unsigned int u32;

// pack two floats to f16x2: low half = lo, high half = hi
__device__ __forceinline__ u32 f16pk(float lo, float hi) {
    u32 d; asm("cvt.rn.f16x2.f32 %0,%1,%2;" : "=r"(d) : "f"(hi), "f"(lo)); return d;
}
// packed relu on an already-packed f16x2
__device__ __forceinline__ u32 max0_pk(u32 v) {
    u32 r; asm("max.f16x2 %0,%1,%2;" : "=r"(r) : "r"(v), "r"(0u)); return r;
}
// accurate tanh (exact identity + fast exp)
__device__ __forceinline__ float tanh_acc(float v) {
    float e = __expf(2.0f * v);
    return 1.0f - __fdividef(2.0f, e + 1.0f);
}

// ---------------- mma / ldmatrix ----------------
// f32-accum variants (final-output layers)
__device__ __forceinline__ void mma_f16_c(float& d0, float& d1, float& d2, float& d3,
                                          u32 a0, u32 a1, u32 a2, u32 a3,
                                          u32 b0, u32 b1, float c0, float c1) {
    asm volatile("mma.sync.aligned.m16n8k16.row.col.f32.f16.f16.f32 "
                 "{%0,%1,%2,%3},{%4,%5,%6,%7},{%8,%9},{%10,%11,%10,%11};"
                 : "=f"(d0), "=f"(d1), "=f"(d2), "=f"(d3)
                 : "r"(a0), "r"(a1), "r"(a2), "r"(a3), "r"(b0), "r"(b1),
                   "f"(c0), "f"(c1));
}
__device__ __forceinline__ void mma_f16_acc(float& d0, float& d1, float& d2, float& d3,
                                            u32 a0, u32 a1, u32 a2, u32 a3,
                                            u32 b0, u32 b1) {
    asm volatile("mma.sync.aligned.m16n8k16.row.col.f32.f16.f16.f32 "
                 "{%0,%1,%2,%3},{%4,%5,%6,%7},{%8,%9},{%0,%1,%2,%3};"
                 : "+f"(d0), "+f"(d1), "+f"(d2), "+f"(d3)
                 : "r"(a0), "r"(a1), "r"(a2), "r"(a3), "r"(b0), "r"(b1));
}
// f16-out: D,C packed f16x2; C = {bp, bp} (same bias pair both row groups)
__device__ __forceinline__ void mma_h16_c(u32& d0, u32& d1,
                                          u32 a0, u32 a1, u32 a2, u32 a3,
                                          u32 b0, u32 b1, u32 bp) {
    asm volatile("mma.sync.aligned.m16n8k16.row.col.f16.f16.f16.f16 "
                 "{%0,%1},{%2,%3,%4,%5},{%6,%7},{%8,%8};"
                 : "=r"(d0), "=r"(d1)
                 : "r"(a0), "r"(a1), "r"(a2), "r"(a3), "r"(b0), "r"(b1), "r"(bp));
}
// f16-out accumulate: D += A*B (C = D)
__device__ __forceinline__ void mma_h16_acc(u32& d0, u32& d1,
                                            u32 a0, u32 a1, u32 a2, u32 a3,
                                            u32 b0, u32 b1) {
    asm volatile("mma.sync.aligned.m16n8k16.row.col.f16.f16.f16.f16 "
                 "{%0,%1},{%2,%3,%4,%5},{%6,%7},{%0,%1};"
                 : "+r"(d0), "+r"(d1)
                 : "r"(a0), "r"(a1), "r"(a2), "r"(a3), "r"(b0), "r"(b1));
}
__device__ __forceinline__ void ldm_x4(u32* r, u32 addr) {
    asm volatile("ldmatrix.sync.aligned.m8n8.x4.shared.b16 {%0,%1,%2,%3}, [%4];"
                 : "=r"(r[0]), "=r"(r[1]), "=r"(r[2]), "=r"(r[3]) : "r"(addr));
}
__device__ __forceinline__ u32 smem_to_u32(const void* p) {
    u32 a;
    asm("{ .reg .u64 t; cvta.to.shared.u64 t, %1; cvt.u32.u64 %0, t; }" : "=r"(a) : "l"(p));
    return a;
}

// ---------------- SMEM layout (bytes) ----------------
#define XB  0        // x fp16 rows: 256 x 48B
#define RB  12288    // rin fp16 rows: 256 x 48B
#define WX  24576    // normalized gate weights [8][256] f32   (8 KB)
#define FU  32768    // expert outputs (unweighted tanh) [8][256] float2 (16 KB)
#define TB2 49152    // expert bias2 packed f16x2 [e][nt][tig] u32 (512B)
#define GT  50176    // gate lane tables: 32 x 272B
#define RT  58880    // refine lane tables: 32 x 272B
#define SMEM_TOTAL 67584
// lane table layout: b1t u32[16] @0, c1p u32[8] @64, b2t u32[8] @96, c2 float2 @128

extern __shared__ char smem_raw[];

__global__ void __launch_bounds__(256, 2)
moe_r15_kernel(const float* __restrict__ X,
               const float* __restrict__ W1, const float* __restrict__ b1,
               const float* __restrict__ W2, const float* __restrict__ b2,
               const float* __restrict__ W3, const float* __restrict__ b3,
               const float* __restrict__ G1, const float* __restrict__ gb1,
               const float* __restrict__ G2, const float* __restrict__ gb2,
               const float* __restrict__ R1, const float* __restrict__ rb1,
               const float* __restrict__ R2, const float* __restrict__ rb2,
               float* __restrict__ out)
{
    const int tid  = threadIdx.x;
    const int wid  = tid >> 5;     // = expert id
    const int lane = tid & 31;
    const int grp  = lane >> 2;
    const int tig  = lane & 3;
    const u32 sbase = smem_to_u32(smem_raw);

    // ---- expert bias2 packed table ----
    if (tid < 128) {
        int te = tid >> 4, tn = (tid >> 2) & 3, tg = tid & 3;
        int c0 = tn * 8 + 2 * tg;
        *reinterpret_cast<u32*>(smem_raw + TB2 + tid * 4) =
            f16pk(b2[te * 32 + c0], b2[te * 32 + c0 + 1]);
    }

    // ---- gate / refine per-lane fragment tables (272B stride, conflict-free) ----
    if (tid < 32) {
        int g = tid >> 2, t = tid & 3;
        int k0 = 2 * t;
        {
            char* gt = smem_raw + GT + tid * 272;
            u32*    b1t = reinterpret_cast<u32*>(gt);
            u32*    c1p = reinterpret_cast<u32*>(gt + 64);
            u32*    b2t = reinterpret_cast<u32*>(gt + 96);
            float2* c2t = reinterpret_cast<float2*>(gt + 128);
            #pragma unroll
            for (int nt = 0; nt < 8; nt++) {
                int n = nt * 8 + g;
                b1t[nt * 2]     = f16pk(G1[k0 * 64 + n], G1[(k0 + 1) * 64 + n]);
                float wa = (k0 + 8 < 10) ? G1[(k0 + 8) * 64 + n] : 0.f;
                float wb = (k0 + 9 < 10) ? G1[(k0 + 9) * 64 + n] : 0.f;
                b1t[nt * 2 + 1] = f16pk(wa, wb);
                c1p[nt] = f16pk(gb1[nt * 8 + k0], gb1[nt * 8 + k0 + 1]);
            }
            #pragma unroll
            for (int kt = 0; kt < 4; kt++) {
                int kk = kt * 16 + k0;
                b2t[kt * 2]     = f16pk(G2[kk * 8 + g],       G2[(kk + 1) * 8 + g]);
                b2t[kt * 2 + 1] = f16pk(G2[(kk + 8) * 8 + g], G2[(kk + 9) * 8 + g]);
            }
            c2t[0] = make_float2(gb2[k0], gb2[k0 + 1]);
        }
        {
            char* rt = smem_raw + RT + tid * 272;
            u32*    b1t = reinterpret_cast<u32*>(rt);
            u32*    c1p = reinterpret_cast<u32*>(rt + 64);
            u32*    b2t = reinterpret_cast<u32*>(rt + 96);
            float2* c2t = reinterpret_cast<float2*>(rt + 128);
            #pragma unroll
            for (int nt = 0; nt < 8; nt++) {
                int n = nt * 8 + g;
                b1t[nt * 2]     = f16pk(R1[k0 * 64 + n], R1[(k0 + 1) * 64 + n]);
                float wa = (k0 + 8 < 12) ? R1[(k0 + 8) * 64 + n] : 0.f;
                float wb = (k0 + 9 < 12) ? R1[(k0 + 9) * 64 + n] : 0.f;
                b1t[nt * 2 + 1] = f16pk(wa, wb);
                c1p[nt] = f16pk(rb1[nt * 8 + k0], rb1[nt * 8 + k0 + 1]);
            }
            #pragma unroll
            for (int kt = 0; kt < 4; kt++) {
                int kk = kt * 16 + k0;
                float wa0 = (g < 2) ? R2[kk * 2 + g] : 0.f;
                float wb0 = (g < 2) ? R2[(kk + 1) * 2 + g] : 0.f;
                b2t[kt * 2]     = f16pk(wa0, wb0);
                float wa1 = (g < 2) ? R2[(kk + 8) * 2 + g] : 0.f;
                float wb1 = (g < 2) ? R2[(kk + 9) * 2 + g] : 0.f;
                b2t[kt * 2 + 1] = f16pk(wa1, wb1);
            }
            c2t[0] = make_float2(t == 0 ? rb2[0] : 0.f, t == 0 ? rb2[1] : 0.f);
        }
    }

    // ---- register-resident fp16 expert fragments (warp e = expert e) ----
    const int e = wid;
    u32 b1f[4][2];            // W1 [nt][b0/b1]
    u32 b2f[4][2][2];         // W2 [nt][kt][b0/b1]
    u32 w3f[2][2];            // W3 [kc][b0/b1], n = grp (zero for grp >= 2)
    u32 bias1p[4];            // packed f16x2 bias pairs for L1
    #pragma unroll
    for (int nt = 0; nt < 4; nt++) {
        int n = nt * 8 + grp;
        b1f[nt][0] = f16pk(W1[e * 320 + (2 * tig) * 32 + n],
                           W1[e * 320 + (2 * tig + 1) * 32 + n]);
        {
            float wa = (2 * tig + 8 < 10) ? W1[e * 320 + (2 * tig + 8) * 32 + n] : 0.f;
            float wb = (2 * tig + 9 < 10) ? W1[e * 320 + (2 * tig + 9) * 32 + n] : 0.f;
            b1f[nt][1] = f16pk(wa, wb);
        }
        #pragma unroll
        for (int kt = 0; kt < 2; kt++) {
            int k0 = kt * 16 + 2 * tig;
            b2f[nt][kt][0] = f16pk(W2[e * 1024 + k0 * 32 + n],
                                   W2[e * 1024 + (k0 + 1) * 32 + n]);
            b2f[nt][kt][1] = f16pk(W2[e * 1024 + (k0 + 8) * 32 + n],
                                   W2[e * 1024 + (k0 + 9) * 32 + n]);
        }
        int c0 = nt * 8 + 2 * tig;
        bias1p[nt] = f16pk(b1[e * 32 + c0], b1[e * 32 + c0 + 1]);
    }
    #pragma unroll
    for (int kc = 0; kc < 2; kc++) {
        int kb = kc * 16;
        float v00 = (grp < 2) ? W3[e * 64 + (kb + 2 * tig) * 2 + grp] : 0.f;
        float v01 = (grp < 2) ? W3[e * 64 + (kb + 2 * tig + 1) * 2 + grp] : 0.f;
        w3f[kc][0] = f16pk(v00, v01);
        float v10 = (grp < 2) ? W3[e * 64 + (kb + 8 + 2 * tig) * 2 + grp] : 0.f;
        float v11 = (grp < 2) ? W3[e * 64 + (kb + 9 + 2 * tig) * 2 + grp] : 0.f;
        w3f[kc][1] = f16pk(v10, v11);
    }
    const float b3e0 = b3[e * 2], b3e1 = b3[e * 2 + 1];
    __syncthreads();

    for (int tile = blockIdx.x; tile < NTILES; tile += gridDim.x) {
        const int tok = tile * 256 + tid;

        // ============ phase 1: load x, stage fp16 rows ============
        u32 xs[5];
        {
            const float2* xp = reinterpret_cast<const float2*>(X + (size_t)tok * 10);
            #pragma unroll
            for (int i = 0; i < 5; i++) {
                float2 v = xp[i];
                xs[i] = f16pk(v.x, v.y);
            }
            uint4* p = reinterpret_cast<uint4*>(smem_raw + XB + tid * 48);
            p[0] = make_uint4(xs[0], xs[1], xs[2], xs[3]);
            p[1] = make_uint4(xs[4], 0u, 0u, 0u);
        }
        __syncthreads();

        // ============ phase 2a: gate via mma (2 m-tiles per warp) ============
        {
            const char* gt = smem_raw + GT + (u32)lane * 272;
            const u32*    b1t = reinterpret_cast<const u32*>(gt);
            const u32*    c1p = reinterpret_cast<const u32*>(gt + 64);
            const u32*    b2t = reinterpret_cast<const u32*>(gt + 96);
            const float2  c2  = *reinterpret_cast<const float2*>(gt + 128);
            float* wxp = reinterpret_cast<float*>(smem_raw + WX);
            #pragma unroll 1
            for (int q = 0; q < 2; q++) {
                int mt = wid * 2 + q;
                u32 ax[4];
                ldm_x4(ax, sbase + XB + (u32)(mt * 16 + (lane & 15)) * 48
                           + ((lane >> 4) << 4));
                // L1: f16-out mma, relu = max.f16x2 (D-frag == next A-frag)
                u32 a2[4][4];
                #pragma unroll
                for (int nt = 0; nt < 8; nt++) {
                    u32 dh0, dh1;
                    mma_h16_c(dh0, dh1, ax[0], ax[1], ax[2], ax[3],
                              b1t[2*nt], b1t[2*nt+1], c1p[nt]);
                    int kt = nt >> 1, hf = (nt & 1) << 1;
                    a2[kt][hf]     = max0_pk(dh0);
                    a2[kt][hf + 1] = max0_pk(dh1);
                }
                // L2 (logits): f32 accum
                float l0, l1, l2, l3;
                mma_f16_c(l0, l1, l2, l3,
                          a2[0][0], a2[0][1], a2[0][2], a2[0][3],
                          b2t[0], b2t[1], c2.x, c2.y);
                #pragma unroll
                for (int kt = 1; kt < 4; kt++)
                    mma_f16_acc(l0, l1, l2, l3,
                                a2[kt][0], a2[kt][1], a2[kt][2], a2[kt][3],
                                b2t[2*kt], b2t[2*kt+1]);
                // softmax per row (8 logits spread over quad, 2 per lane)
                float mA = fmaxf(l0, l1);
                mA = fmaxf(mA, __shfl_xor_sync(0xFFFFFFFFu, mA, 1));
                mA = fmaxf(mA, __shfl_xor_sync(0xFFFFFFFFu, mA, 2));
                float eA0 = __expf(l0 - mA), eA1 = __expf(l1 - mA);
                float sA = eA0 + eA1;
                sA += __shfl_xor_sync(0xFFFFFFFFu, sA, 1);
                sA += __shfl_xor_sync(0xFFFFFFFFu, sA, 2);
                float iA = __fdividef(1.f, sA);
                float mB = fmaxf(l2, l3);
                mB = fmaxf(mB, __shfl_xor_sync(0xFFFFFFFFu, mB, 1));
                mB = fmaxf(mB, __shfl_xor_sync(0xFFFFFFFFu, mB, 2));
                float eB0 = __expf(l2 - mB), eB1 = __expf(l3 - mB);
                float sB = eB0 + eB1;
                sB += __shfl_xor_sync(0xFFFFFFFFu, sB, 1);
                sB += __shfl_xor_sync(0xFFFFFFFFu, sB, 2);
                float iB = __fdividef(1.f, sB);
                int rowA = mt * 16 + grp;
                wxp[(2*tig)   * 256 + rowA]     = eA0 * iA;
                wxp[(2*tig+1) * 256 + rowA]     = eA1 * iA;
                wxp[(2*tig)   * 256 + rowA + 8] = eB0 * iB;
                wxp[(2*tig+1) * 256 + rowA + 8] = eB1 * iB;
            }
        }

        // ============ phase 2b: expert GEMMs (warp = expert, 16 m-tiles) ============
        {
            float2* fup = reinterpret_cast<float2*>(smem_raw + FU);
            const u32 tb2p = *reinterpret_cast<const u32*>(smem_raw + TB2);  // dummy init avoided; loaded per nt below
            (void)tb2p;
            #pragma unroll 1
            for (int mt = 0; mt < 16; mt++) {
                u32 ax[4];
                ldm_x4(ax, sbase + XB + (u32)(mt * 16 + (lane & 15)) * 48
                           + ((lane >> 4) << 4));
                // L1: f16-out mma (bias in packed C), relu = max.f16x2
                u32 a2[2][4];
                #pragma unroll
                for (int nt = 0; nt < 4; nt++) {
                    u32 dh0, dh1;
                    mma_h16_c(dh0, dh1, ax[0], ax[1], ax[2], ax[3],
                              b1f[nt][0], b1f[nt][1], bias1p[nt]);
                    int kt = nt >> 1, hf = (nt & 1) << 1;
                    a2[kt][hf]     = max0_pk(dh0);
                    a2[kt][hf + 1] = max0_pk(dh1);
                }
                // L2: f16-out mma pair (bias2 packed in C), relu = max.f16x2
                u32 p3[4][2];
                #pragma unroll
                for (int nt = 0; nt < 4; nt++) {
                    u32 tb = *reinterpret_cast<const u32*>(
                        smem_raw + TB2 + (u32)(((e * 4 + nt) * 4 + tig)) * 4);
                    u32 gh0, gh1;
                    mma_h16_c(gh0, gh1,
                              a2[0][0], a2[0][1], a2[0][2], a2[0][3],
                              b2f[nt][0][0], b2f[nt][0][1], tb);
                    mma_h16_acc(gh0, gh1,
                                a2[1][0], a2[1][1], a2[1][2], a2[1][3],
                                b2f[nt][1][0], b2f[nt][1][1]);
                    p3[nt][0] = max0_pk(gh0);
                    p3[nt][1] = max0_pk(gh1);
                }
                // L3 via f32-accum mma pair (bias3 in C); cols 0,1 on tig==0
                float y0, y1, y2, y3;
                mma_f16_c(y0, y1, y2, y3,
                          p3[0][0], p3[0][1], p3[1][0], p3[1][1],
                          w3f[0][0], w3f[0][1], b3e0, b3e1);
                mma_f16_acc(y0, y1, y2, y3,
                            p3[2][0], p3[2][1], p3[3][0], p3[3][1],
                            w3f[1][0], w3f[1][1]);
                if (tig == 0) {
                    int tk = mt * 16 + grp;
                    fup[e * 256 + tk]     = make_float2(tanh_acc(y0), tanh_acc(y1));
                    fup[e * 256 + tk + 8] = make_float2(tanh_acc(y2), tanh_acc(y3));
                }
            }
        }
        __syncthreads();

        // ============ phase 3: fuse + restage rin ============
        {
            const float2* fup = reinterpret_cast<const float2*>(smem_raw + FU);
            const float* wxp = reinterpret_cast<const float*>(smem_raw + WX);
            float f0 = 0.f, f1 = 0.f;
            #pragma unroll
            for (int q2 = 0; q2 < 8; q2++) {
                float2 s = fup[q2 * 256 + tid];
                float w = wxp[q2 * 256 + tid];
                f0 += w * s.x; f1 += w * s.y;
            }
            uint4* p = reinterpret_cast<uint4*>(smem_raw + RB + tid * 48);
            p[0] = make_uint4(f16pk(f0, f1), xs[0], xs[1], xs[2]);
            p[1] = make_uint4(xs[3], xs[4], 0u, 0u);
        }
        __syncthreads();

        // ============ phase 4: refine via mma (2 m-tiles per warp) ============
        {
            const char* rt = smem_raw + RT + (u32)lane * 272;
            const u32*    b1t = reinterpret_cast<const u32*>(rt);
            const u32*    c1p = reinterpret_cast<const u32*>(rt + 64);
            const u32*    b2t = reinterpret_cast<const u32*>(rt + 96);
            const float2  c2  = *reinterpret_cast<const float2*>(rt + 128);
            float2* out2 = reinterpret_cast<float2*>(out);
            #pragma unroll 1
            for (int q = 0; q < 2; q++) {
                int mt = wid * 2 + q;
                u32 ax[4];
                ldm_x4(ax, sbase + RB + (u32)(mt * 16 + (lane & 15)) * 48
                           + ((lane >> 4) << 4));
                // L1: f16-out mma, relu = max.f16x2
                u32 a2[4][4];
                #pragma unroll
                for (int nt = 0; nt < 8; nt++) {
                    u32 dh0, dh1;
                    mma_h16_c(dh0, dh1, ax[0], ax[1], ax[2], ax[3],
                              b1t[2*nt], b1t[2*nt+1], c1p[nt]);
                    int kt = nt >> 1, hf = (nt & 1) << 1;
                    a2[kt][hf]     = max0_pk(dh0);
                    a2[kt][hf + 1] = max0_pk(dh1);
                }
                // L2 (final): f32 accum
                float y0, y1, y2, y3;
                mma_f16_c(y0, y1, y2, y3,
                          a2[0][0], a2[0][1], a2[0][2], a2[0][3],
                          b2t[0], b2t[1], c2.x, c2.y);
                #pragma unroll
                for (int kt = 1; kt < 4; kt++)
                    mma_f16_acc(y0, y1, y2, y3,
                                a2[kt][0], a2[kt][1], a2[kt][2], a2[kt][3],
                                b2t[2*kt], b2t[2*kt+1]);
                if (tig == 0) {
                    int rowA = tile * 256 + mt * 16 + grp;
                    out2[rowA]     = make_float2(tanh_acc(y0), tanh_acc(y1));
                    out2[rowA + 8] = make_float2(tanh_acc(y2), tanh_acc(y3));
                }
            }
        }
    }
}

extern "C" void kernel_launch(void* const* d_in, const int* in_sizes, int n_in,
                              void* d_out, int out_size)
{
    (void)in_sizes; (void)n_in; (void)out_size;
    const float* X   = (const float*)d_in[0];
    const float* W1  = (const float*)d_in[1];
    const float* b1  = (const float*)d_in[2];
    const float* W2  = (const float*)d_in[3];
    const float* b2  = (const float*)d_in[4];
    const float* W3  = (const float*)d_in[5];
    const float* b3  = (const float*)d_in[6];
    const float* G1  = (const float*)d_in[7];
    const float* gb1 = (const float*)d_in[8];
    const float* G2  = (const float*)d_in[9];
    const float* gb2 = (const float*)d_in[10];
    const float* R1  = (const float*)d_in[11];
    const float* rb1 = (const float*)d_in[12];
    const float* R2  = (const float*)d_in[13];
    const float* rb2 = (const float*)d_in[14];

    cudaFuncSetAttribute(moe_r15_kernel,
                         cudaFuncAttributeMaxDynamicSharedMemorySize, SMEM_TOTAL);

    moe_r15_kernel<<<GRID, 256, SMEM_TOTAL>>>(
        X, W1, b1, W2, b2, W3, b3, G1, gb1, G2, gb2, R1, rb1, R2, rb2,
        (float*)d_out);
}

// round 16
// speedup vs baseline: 1.7960x; 1.1447x over previous
#include <cuda_runtime.h>
#include <cuda_fp16.h>
#include <cstdint>

// Round 16: R15 (127.1us) + (a) expert tanh moved from divergent tig==0
// epilogue to full-width phase 3 (same math, 4x fewer warp-level chains),
// (b) bias2 table hoisted to registers outside the persistent loop.
// CTA = 256 threads = 8 warps (warp e = expert e), tile = 256 tokens.

#define NTILES 4096
#define GRID   592

typedef unsigned int u32;

__device__ __forceinline__ u32 f16pk(float lo, float hi) {
    u32 d; asm("cvt.rn.f16x2.f32 %0,%1,%2;" : "=r"(d) : "f"(hi), "f"(lo)); return d;
}
__device__ __forceinline__ u32 max0_pk(u32 v) {
    u32 r; asm("max.f16x2 %0,%1,%2;" : "=r"(r) : "r"(v), "r"(0u)); return r;
}
__device__ __forceinline__ float tanh_acc(float v) {
    float e = __expf(2.0f * v);
    return 1.0f - __fdividef(2.0f, e + 1.0f);
}

// ---------------- mma / ldmatrix ----------------
__device__ __forceinline__ void mma_f16_c(float& d0, float& d1, float& d2, float& d3,
                                          u32 a0, u32 a1, u32 a2, u32 a3,
                                          u32 b0, u32 b1, float c0, float c1) {
    asm volatile("mma.sync.aligned.m16n8k16.row.col.f32.f16.f16.f32 "
                 "{%0,%1,%2,%3},{%4,%5,%6,%7},{%8,%9},{%10,%11,%10,%11};"
                 : "=f"(d0), "=f"(d1), "=f"(d2), "=f"(d3)
                 : "r"(a0), "r"(a1), "r"(a2), "r"(a3), "r"(b0), "r"(b1),
                   "f"(c0), "f"(c1));
}
__device__ __forceinline__ void mma_f16_acc(float& d0, float& d1, float& d2, float& d3,
                                            u32 a0, u32 a1, u32 a2, u32 a3,
                                            u32 b0, u32 b1) {
    asm volatile("mma.sync.aligned.m16n8k16.row.col.f32.f16.f16.f32 "
                 "{%0,%1,%2,%3},{%4,%5,%6,%7},{%8,%9},{%0,%1,%2,%3};"
                 : "+f"(d0), "+f"(d1), "+f"(d2), "+f"(d3)
                 : "r"(a0), "r"(a1), "r"(a2), "r"(a3), "r"(b0), "r"(b1));
}
__device__ __forceinline__ void mma_h16_c(u32& d0, u32& d1,
                                          u32 a0, u32 a1, u32 a2, u32 a3,
                                          u32 b0, u32 b1, u32 bp) {
    asm volatile("mma.sync.aligned.m16n8k16.row.col.f16.f16.f16.f16 "
                 "{%0,%1},{%2,%3,%4,%5},{%6,%7},{%8,%8};"
                 : "=r"(d0), "=r"(d1)
                 : "r"(a0), "r"(a1), "r"(a2), "r"(a3), "r"(b0), "r"(b1), "r"(bp));
}
__device__ __forceinline__ void mma_h16_acc(u32& d0, u32& d1,
                                            u32 a0, u32 a1, u32 a2, u32 a3,
                                            u32 b0, u32 b1) {
    asm volatile("mma.sync.aligned.m16n8k16.row.col.f16.f16.f16.f16 "
                 "{%0,%1},{%2,%3,%4,%5},{%6,%7},{%0,%1};"
                 : "+r"(d0), "+r"(d1)
                 : "r"(a0), "r"(a1), "r"(a2), "r"(a3), "r"(b0), "r"(b1));
}
__device__ __forceinline__ void ldm_x4(u32* r, u32 addr) {
    asm volatile("ldmatrix.sync.aligned.m8n8.x4.shared.b16 {%0,%1,%2,%3}, [%4];"
                 : "=r"(r[0]), "=r"(r[1]), "=r"(r[2]), "=r"(r[3]) : "r"(addr));
}
__device__ __forceinline__ u32 smem_to_u32(const void* p) {
    u32 a;
    asm("{ .reg .u64 t; cvta.to.shared.u64 t, %1; cvt.u32.u64 %0, t; }" : "=r"(a) : "l"(p));
    return a;
}

// ---------------- SMEM layout (bytes) ----------------
#define XB  0        // x fp16 rows: 256 x 48B
#define RB  12288    // rin fp16 rows: 256 x 48B
#define WX  24576    // normalized gate weights [8][256] f32   (8 KB)
#define FU  32768    // expert outputs (pre-tanh) [8][256] float2 (16 KB)
#define TB2 49152    // expert bias2 packed f16x2 [e][nt][tig] u32 (512B)
#define GT  50176    // gate lane tables: 32 x 272B
#define RT  58880    // refine lane tables: 32 x 272B
#define SMEM_TOTAL 67584
// lane table layout: b1t u32[16] @0, c1p u32[8] @64, b2t u32[8] @96, c2 float2 @128

extern __shared__ char smem_raw[];

__global__ void __launch_bounds__(256, 2)
moe_r16_kernel(const float* __restrict__ X,
               const float* __restrict__ W1, const float* __restrict__ b1,
               const float* __restrict__ W2, const float* __restrict__ b2,
               const float* __restrict__ W3, const float* __restrict__ b3,
               const float* __restrict__ G1, const float* __restrict__ gb1,
               const float* __restrict__ G2, const float* __restrict__ gb2,
               const float* __restrict__ R1, const float* __restrict__ rb1,
               const float* __restrict__ R2, const float* __restrict__ rb2,
               float* __restrict__ out)
{
    const int tid  = threadIdx.x;
    const int wid  = tid >> 5;     // = expert id
    const int lane = tid & 31;
    const int grp  = lane >> 2;
    const int tig  = lane & 3;
    const u32 sbase = smem_to_u32(smem_raw);

    // ---- expert bias2 packed table ----
    if (tid < 128) {
        int te = tid >> 4, tn = (tid >> 2) & 3, tg = tid & 3;
        int c0 = tn * 8 + 2 * tg;
        *reinterpret_cast<u32*>(smem_raw + TB2 + tid * 4) =
            f16pk(b2[te * 32 + c0], b2[te * 32 + c0 + 1]);
    }

    // ---- gate / refine per-lane fragment tables (272B stride, conflict-free) ----
    if (tid < 32) {
        int g = tid >> 2, t = tid & 3;
        int k0 = 2 * t;
        {
            char* gt = smem_raw + GT + tid * 272;
            u32*    b1t = reinterpret_cast<u32*>(gt);
            u32*    c1p = reinterpret_cast<u32*>(gt + 64);
            u32*    b2t = reinterpret_cast<u32*>(gt + 96);
            float2* c2t = reinterpret_cast<float2*>(gt + 128);
            #pragma unroll
            for (int nt = 0; nt < 8; nt++) {
                int n = nt * 8 + g;
                b1t[nt * 2]     = f16pk(G1[k0 * 64 + n], G1[(k0 + 1) * 64 + n]);
                float wa = (k0 + 8 < 10) ? G1[(k0 + 8) * 64 + n] : 0.f;
                float wb = (k0 + 9 < 10) ? G1[(k0 + 9) * 64 + n] : 0.f;
                b1t[nt * 2 + 1] = f16pk(wa, wb);
                c1p[nt] = f16pk(gb1[nt * 8 + k0], gb1[nt * 8 + k0 + 1]);
            }
            #pragma unroll
            for (int kt = 0; kt < 4; kt++) {
                int kk = kt * 16 + k0;
                b2t[kt * 2]     = f16pk(G2[kk * 8 + g],       G2[(kk + 1) * 8 + g]);
                b2t[kt * 2 + 1] = f16pk(G2[(kk + 8) * 8 + g], G2[(kk + 9) * 8 + g]);
            }
            c2t[0] = make_float2(gb2[k0], gb2[k0 + 1]);
        }
        {
            char* rt = smem_raw + RT + tid * 272;
            u32*    b1t = reinterpret_cast<u32*>(rt);
            u32*    c1p = reinterpret_cast<u32*>(rt + 64);
            u32*    b2t = reinterpret_cast<u32*>(rt + 96);
            float2* c2t = reinterpret_cast<float2*>(rt + 128);
            #pragma unroll
            for (int nt = 0; nt < 8; nt++) {
                int n = nt * 8 + g;
                b1t[nt * 2]     = f16pk(R1[k0 * 64 + n], R1[(k0 + 1) * 64 + n]);
                float wa = (k0 + 8 < 12) ? R1[(k0 + 8) * 64 + n] : 0.f;
                float wb = (k0 + 9 < 12) ? R1[(k0 + 9) * 64 + n] : 0.f;
                b1t[nt * 2 + 1] = f16pk(wa, wb);
                c1p[nt] = f16pk(rb1[nt * 8 + k0], rb1[nt * 8 + k0 + 1]);
            }
            #pragma unroll
            for (int kt = 0; kt < 4; kt++) {
                int kk = kt * 16 + k0;
                float wa0 = (g < 2) ? R2[kk * 2 + g] : 0.f;
                float wb0 = (g < 2) ? R2[(kk + 1) * 2 + g] : 0.f;
                b2t[kt * 2]     = f16pk(wa0, wb0);
                float wa1 = (g < 2) ? R2[(kk + 8) * 2 + g] : 0.f;
                float wb1 = (g < 2) ? R2[(kk + 9) * 2 + g] : 0.f;
                b2t[kt * 2 + 1] = f16pk(wa1, wb1);
            }
            c2t[0] = make_float2(t == 0 ? rb2[0] : 0.f, t == 0 ? rb2[1] : 0.f);
        }
    }

    // ---- register-resident fp16 expert fragments (warp e = expert e) ----
    const int e = wid;
    u32 b1f[4][2];            // W1 [nt][b0/b1]
    u32 b2f[4][2][2];         // W2 [nt][kt][b0/b1]
    u32 w3f[2][2];            // W3 [kc][b0/b1], n = grp (zero for grp >= 2)
    u32 bias1p[4];            // packed f16x2 bias pairs for L1
    #pragma unroll
    for (int nt = 0; nt < 4; nt++) {
        int n = nt * 8 + grp;
        b1f[nt][0] = f16pk(W1[e * 320 + (2 * tig) * 32 + n],
                           W1[e * 320 + (2 * tig + 1) * 32 + n]);
        {
            float wa = (2 * tig + 8 < 10) ? W1[e * 320 + (2 * tig + 8) * 32 + n] : 0.f;
            float wb = (2 * tig + 9 < 10) ? W1[e * 320 + (2 * tig + 9) * 32 + n] : 0.f;
            b1f[nt][1] = f16pk(wa, wb);
        }
        #pragma unroll
        for (int kt = 0; kt < 2; kt++) {
            int k0 = kt * 16 + 2 * tig;
            b2f[nt][kt][0] = f16pk(W2[e * 1024 + k0 * 32 + n],
                                   W2[e * 1024 + (k0 + 1) * 32 + n]);
            b2f[nt][kt][1] = f16pk(W2[e * 1024 + (k0 + 8) * 32 + n],
                                   W2[e * 1024 + (k0 + 9) * 32 + n]);
        }
        int c0 = nt * 8 + 2 * tig;
        bias1p[nt] = f16pk(b1[e * 32 + c0], b1[e * 32 + c0 + 1]);
    }
    #pragma unroll
    for (int kc = 0; kc < 2; kc++) {
        int kb = kc * 16;
        float v00 = (grp < 2) ? W3[e * 64 + (kb + 2 * tig) * 2 + grp] : 0.f;
        float v01 = (grp < 2) ? W3[e * 64 + (kb + 2 * tig + 1) * 2 + grp] : 0.f;
        w3f[kc][0] = f16pk(v00, v01);
        float v10 = (grp < 2) ? W3[e * 64 + (kb + 8 + 2 * tig) * 2 + grp] : 0.f;
        float v11 = (grp < 2) ? W3[e * 64 + (kb + 9 + 2 * tig) * 2 + grp] : 0.f;
        w3f[kc][1] = f16pk(v10, v11);
    }
    const float b3e0 = b3[e * 2], b3e1 = b3[e * 2 + 1];
    __syncthreads();

    // hoisted bias2 fragments (constant for the whole kernel)
    u32 tb2r[4];
    #pragma unroll
    for (int nt = 0; nt < 4; nt++)
        tb2r[nt] = *reinterpret_cast<const u32*>(
            smem_raw + TB2 + (u32)(((e * 4 + nt) * 4 + tig)) * 4);

    for (int tile = blockIdx.x; tile < NTILES; tile += gridDim.x) {
        const int tok = tile * 256 + tid;

        // ============ phase 1: load x, stage fp16 rows ============
        u32 xs[5];
        {
            const float2* xp = reinterpret_cast<const float2*>(X + (size_t)tok * 10);
            #pragma unroll
            for (int i = 0; i < 5; i++) {
                float2 v = xp[i];
                xs[i] = f16pk(v.x, v.y);
            }
            uint4* p = reinterpret_cast<uint4*>(smem_raw + XB + tid * 48);
            p[0] = make_uint4(xs[0], xs[1], xs[2], xs[3]);
            p[1] = make_uint4(xs[4], 0u, 0u, 0u);
        }
        __syncthreads();

        // ============ phase 2a: gate via mma (2 m-tiles per warp) ============
        {
            const char* gt = smem_raw + GT + (u32)lane * 272;
            const u32*    b1t = reinterpret_cast<const u32*>(gt);
            const u32*    c1p = reinterpret_cast<const u32*>(gt + 64);
            const u32*    b2t = reinterpret_cast<const u32*>(gt + 96);
            const float2  c2  = *reinterpret_cast<const float2*>(gt + 128);
            float* wxp = reinterpret_cast<float*>(smem_raw + WX);
            #pragma unroll 1
            for (int q = 0; q < 2; q++) {
                int mt = wid * 2 + q;
                u32 ax[4];
                ldm_x4(ax, sbase + XB + (u32)(mt * 16 + (lane & 15)) * 48
                           + ((lane >> 4) << 4));
                u32 a2[4][4];
                #pragma unroll
                for (int nt = 0; nt < 8; nt++) {
                    u32 dh0, dh1;
                    mma_h16_c(dh0, dh1, ax[0], ax[1], ax[2], ax[3],
                              b1t[2*nt], b1t[2*nt+1], c1p[nt]);
                    int kt = nt >> 1, hf = (nt & 1) << 1;
                    a2[kt][hf]     = max0_pk(dh0);
                    a2[kt][hf + 1] = max0_pk(dh1);
                }
                float l0, l1, l2, l3;
                mma_f16_c(l0, l1, l2, l3,
                          a2[0][0], a2[0][1], a2[0][2], a2[0][3],
                          b2t[0], b2t[1], c2.x, c2.y);
                #pragma unroll
                for (int kt = 1; kt < 4; kt++)
                    mma_f16_acc(l0, l1, l2, l3,
                                a2[kt][0], a2[kt][1], a2[kt][2], a2[kt][3],
                                b2t[2*kt], b2t[2*kt+1]);
                // softmax per row
                float mA = fmaxf(l0, l1);
                mA = fmaxf(mA, __shfl_xor_sync(0xFFFFFFFFu, mA, 1));
                mA = fmaxf(mA, __shfl_xor_sync(0xFFFFFFFFu, mA, 2));
                float eA0 = __expf(l0 - mA), eA1 = __expf(l1 - mA);
                float sA = eA0 + eA1;
                sA += __shfl_xor_sync(0xFFFFFFFFu, sA, 1);
                sA += __shfl_xor_sync(0xFFFFFFFFu, sA, 2);
                float iA = __fdividef(1.f, sA);
                float mB = fmaxf(l2, l3);
                mB = fmaxf(mB, __shfl_xor_sync(0xFFFFFFFFu, mB, 1));
                mB = fmaxf(mB, __shfl_xor_sync(0xFFFFFFFFu, mB, 2));
                float eB0 = __expf(l2 - mB), eB1 = __expf(l3 - mB);
                float sB = eB0 + eB1;
                sB += __shfl_xor_sync(0xFFFFFFFFu, sB, 1);
                sB += __shfl_xor_sync(0xFFFFFFFFu, sB, 2);
                float iB = __fdividef(1.f, sB);
                int rowA = mt * 16 + grp;
                wxp[(2*tig)   * 256 + rowA]     = eA0 * iA;
                wxp[(2*tig+1) * 256 + rowA]     = eA1 * iA;
                wxp[(2*tig)   * 256 + rowA + 8] = eB0 * iB;
                wxp[(2*tig+1) * 256 + rowA + 8] = eB1 * iB;
            }
        }

        // ============ phase 2b: expert GEMMs (warp = expert, 16 m-tiles) ============
        {
            float2* fup = reinterpret_cast<float2*>(smem_raw + FU);
            #pragma unroll 1
            for (int mt = 0; mt < 16; mt++) {
                u32 ax[4];
                ldm_x4(ax, sbase + XB + (u32)(mt * 16 + (lane & 15)) * 48
                           + ((lane >> 4) << 4));
                // L1: f16-out mma (bias in packed C), relu = max.f16x2
                u32 a2[2][4];
                #pragma unroll
                for (int nt = 0; nt < 4; nt++) {
                    u32 dh0, dh1;
                    mma_h16_c(dh0, dh1, ax[0], ax[1], ax[2], ax[3],
                              b1f[nt][0], b1f[nt][1], bias1p[nt]);
                    int kt = nt >> 1, hf = (nt & 1) << 1;
                    a2[kt][hf]     = max0_pk(dh0);
                    a2[kt][hf + 1] = max0_pk(dh1);
                }
                // L2: f16-out mma pair (hoisted bias2 in C), relu = max.f16x2
                u32 p3[4][2];
                #pragma unroll
                for (int nt = 0; nt < 4; nt++) {
                    u32 gh0, gh1;
                    mma_h16_c(gh0, gh1,
                              a2[0][0], a2[0][1], a2[0][2], a2[0][3],
                              b2f[nt][0][0], b2f[nt][0][1], tb2r[nt]);
                    mma_h16_acc(gh0, gh1,
                                a2[1][0], a2[1][1], a2[1][2], a2[1][3],
                                b2f[nt][1][0], b2f[nt][1][1]);
                    p3[nt][0] = max0_pk(gh0);
                    p3[nt][1] = max0_pk(gh1);
                }
                // L3 via f32-accum mma pair (bias3 in C); cols 0,1 on tig==0
                float y0, y1, y2, y3;
                mma_f16_c(y0, y1, y2, y3,
                          p3[0][0], p3[0][1], p3[1][0], p3[1][1],
                          w3f[0][0], w3f[0][1], b3e0, b3e1);
                mma_f16_acc(y0, y1, y2, y3,
                            p3[2][0], p3[2][1], p3[3][0], p3[3][1],
                            w3f[1][0], w3f[1][1]);
                if (tig == 0) {
                    int tk = mt * 16 + grp;
                    fup[e * 256 + tk]     = make_float2(y0, y1);   // pre-tanh
                    fup[e * 256 + tk + 8] = make_float2(y2, y3);
                }
            }
        }
        __syncthreads();

        // ============ phase 3: tanh + fuse + restage rin (full-width) ============
        {
            const float2* fup = reinterpret_cast<const float2*>(smem_raw + FU);
            const float* wxp = reinterpret_cast<const float*>(smem_raw + WX);
            float f0 = 0.f, f1 = 0.f;
            #pragma unroll
            for (int q2 = 0; q2 < 8; q2++) {
                float2 s = fup[q2 * 256 + tid];
                float w = wxp[q2 * 256 + tid];
                f0 += w * tanh_acc(s.x);
                f1 += w * tanh_acc(s.y);
            }
            uint4* p = reinterpret_cast<uint4*>(smem_raw + RB + tid * 48);
            p[0] = make_uint4(f16pk(f0, f1), xs[0], xs[1], xs[2]);
            p[1] = make_uint4(xs[3], xs[4], 0u, 0u);
        }
        __syncthreads();

        // ============ phase 4: refine via mma (2 m-tiles per warp) ============
        {
            const char* rt = smem_raw + RT + (u32)lane * 272;
            const u32*    b1t = reinterpret_cast<const u32*>(rt);
            const u32*    c1p = reinterpret_cast<const u32*>(rt + 64);
            const u32*    b2t = reinterpret_cast<const u32*>(rt + 96);
            const float2  c2  = *reinterpret_cast<const float2*>(rt + 128);
            float2* out2 = reinterpret_cast<float2*>(out);
            #pragma unroll 1
            for (int q = 0; q < 2; q++) {
                int mt = wid * 2 + q;
                u32 ax[4];
                ldm_x4(ax, sbase + RB + (u32)(mt * 16 + (lane & 15)) * 48
                           + ((lane >> 4) << 4));
                u32 a2[4][4];
                #pragma unroll
                for (int nt = 0; nt < 8; nt++) {
                    u32 dh0, dh1;
                    mma_h16_c(dh0, dh1, ax[0], ax[1], ax[2], ax[3],
                              b1t[2*nt], b1t[2*nt+1], c1p[nt]);
                    int kt = nt >> 1, hf = (nt & 1) << 1;
                    a2[kt][hf]     = max0_pk(dh0);
                    a2[kt][hf + 1] = max0_pk(dh1);
                }
                float y0, y1, y2, y3;
                mma_f16_c(y0, y1, y2, y3,
                          a2[0][0], a2[0][1], a2[0][2], a2[0][3],
                          b2t[0], b2t[1], c2.x, c2.y);
                #pragma unroll
                for (int kt = 1; kt < 4; kt++)
                    mma_f16_acc(y0, y1, y2, y3,
                                a2[kt][0], a2[kt][1], a2[kt][2], a2[kt][3],
                                b2t[2*kt], b2t[2*kt+1]);
                if (tig == 0) {
                    int rowA = tile * 256 + mt * 16 + grp;
                    out2[rowA]     = make_float2(tanh_acc(y0), tanh_acc(y1));
                    out2[rowA + 8] = make_float2(tanh_acc(y2), tanh_acc(y3));
                }
            }
        }
    }
}

extern "C" void kernel_launch(void* const* d_in, const int* in_sizes, int n_in,
                              void* d_out, int out_size)
{
    (void)in_sizes; (void)n_in; (void)out_size;
    const float* X   = (const float*)d_in[0];
    const float* W1  = (const float*)d_in[1];
    const float* b1  = (const float*)d_in[2];
    const float* W2  = (const float*)d_in[3];
    const float* b2  = (const float*)d_in[4];
    const float* W3  = (const float*)d_in[5];
    const float* b3  = (const float*)d_in[6];
    const float* G1  = (const float*)d_in[7];
    const float* gb1 = (const float*)d_in[8];
    const float* G2  = (const float*)d_in[9];
    const float* gb2 = (const float*)d_in[10];
    const float* R1  = (const float*)d_in[11];
    const float* rb1 = (const float*)d_in[12];
    const float* R2  = (const float*)d_in[13];
    const float* rb2 = (const float*)d_in[14];

    cudaFuncSetAttribute(moe_r16_kernel,
                         cudaFuncAttributeMaxDynamicSharedMemorySize, SMEM_TOTAL);

    moe_r16_kernel<<<GRID, 256, SMEM_TOTAL>>>(
        X, W1, b1, W2, b2, W3, b3, G1, gb1, G2, gb2, R1, rb1, R2, rb2,
        (float*)d_out);
}

// round 17
// speedup vs baseline: 1.8356x; 1.0221x over previous
#include <cuda_runtime.h>
#include <cuda_fp16.h>
#include <cstdint>

// Round 17: 2 experts per warp for 2x in-warp ILP on the expert chain.
// CTA = 128 threads = 4 warps (warp w owns experts 2w, 2w+1), tile = 256
// tokens, 3 CTAs/SM (reg budget 170). All R16 numerics preserved.

#define NTILES 4096
#define GRID   444

typedef unsigned int u32;

__device__ __forceinline__ u32 f16pk(float lo, float hi) {
    u32 d; asm("cvt.rn.f16x2.f32 %0,%1,%2;" : "=r"(d) : "f"(hi), "f"(lo)); return d;
}
__device__ __forceinline__ u32 max0_pk(u32 v) {
    u32 r; asm("max.f16x2 %0,%1,%2;" : "=r"(r) : "r"(v), "r"(0u)); return r;
}
__device__ __forceinline__ float tanh_acc(float v) {
    float e = __expf(2.0f * v);
    return 1.0f - __fdividef(2.0f, e + 1.0f);
}

// ---------------- mma / ldmatrix ----------------
__device__ __forceinline__ void mma_f16_c(float& d0, float& d1, float& d2, float& d3,
                                          u32 a0, u32 a1, u32 a2, u32 a3,
                                          u32 b0, u32 b1, float c0, float c1) {
    asm volatile("mma.sync.aligned.m16n8k16.row.col.f32.f16.f16.f32 "
                 "{%0,%1,%2,%3},{%4,%5,%6,%7},{%8,%9},{%10,%11,%10,%11};"
                 : "=f"(d0), "=f"(d1), "=f"(d2), "=f"(d3)
                 : "r"(a0), "r"(a1), "r"(a2), "r"(a3), "r"(b0), "r"(b1),
                   "f"(c0), "f"(c1));
}
__device__ __forceinline__ void mma_f16_acc(float& d0, float& d1, float& d2, float& d3,
                                            u32 a0, u32 a1, u32 a2, u32 a3,
                                            u32 b0, u32 b1) {
    asm volatile("mma.sync.aligned.m16n8k16.row.col.f32.f16.f16.f32 "
                 "{%0,%1,%2,%3},{%4,%5,%6,%7},{%8,%9},{%0,%1,%2,%3};"
                 : "+f"(d0), "+f"(d1), "+f"(d2), "+f"(d3)
                 : "r"(a0), "r"(a1), "r"(a2), "r"(a3), "r"(b0), "r"(b1));
}
__device__ __forceinline__ void mma_h16_c(u32& d0, u32& d1,
                                          u32 a0, u32 a1, u32 a2, u32 a3,
                                          u32 b0, u32 b1, u32 bp) {
    asm volatile("mma.sync.aligned.m16n8k16.row.col.f16.f16.f16.f16 "
                 "{%0,%1},{%2,%3,%4,%5},{%6,%7},{%8,%8};"
                 : "=r"(d0), "=r"(d1)
                 : "r"(a0), "r"(a1), "r"(a2), "r"(a3), "r"(b0), "r"(b1), "r"(bp));
}
__device__ __forceinline__ void mma_h16_acc(u32& d0, u32& d1,
                                            u32 a0, u32 a1, u32 a2, u32 a3,
                                            u32 b0, u32 b1) {
    asm volatile("mma.sync.aligned.m16n8k16.row.col.f16.f16.f16.f16 "
                 "{%0,%1},{%2,%3,%4,%5},{%6,%7},{%0,%1};"
                 : "+r"(d0), "+r"(d1)
                 : "r"(a0), "r"(a1), "r"(a2), "r"(a3), "r"(b0), "r"(b1));
}
__device__ __forceinline__ void ldm_x4(u32* r, u32 addr) {
    asm volatile("ldmatrix.sync.aligned.m8n8.x4.shared.b16 {%0,%1,%2,%3}, [%4];"
                 : "=r"(r[0]), "=r"(r[1]), "=r"(r[2]), "=r"(r[3]) : "r"(addr));
}
__device__ __forceinline__ u32 smem_to_u32(const void* p) {
    u32 a;
    asm("{ .reg .u64 t; cvta.to.shared.u64 t, %1; cvt.u32.u64 %0, t; }" : "=r"(a) : "l"(p));
    return a;
}

// ---------------- SMEM layout (bytes) ----------------
#define XB  0        // x fp16 rows: 256 x 48B
#define RB  12288    // rin fp16 rows: 256 x 48B
#define WX  24576    // normalized gate weights [8][256] f32   (8 KB)
#define FU  32768    // expert outputs (pre-tanh) [8][256] float2 (16 KB)
#define TB2 49152    // expert bias2 packed f16x2 [e][nt][tig] u32 (512B)
#define GT  50176    // gate lane tables: 32 x 272B
#define RT  58880    // refine lane tables: 32 x 272B
#define SMEM_TOTAL 67584
// lane table layout: b1t u32[16] @0, c1p u32[8] @64, b2t u32[8] @96, c2 float2 @128

extern __shared__ char smem_raw[];

__global__ void __launch_bounds__(128, 3)
moe_r17_kernel(const float* __restrict__ X,
               const float* __restrict__ W1, const float* __restrict__ b1,
               const float* __restrict__ W2, const float* __restrict__ b2,
               const float* __restrict__ W3, const float* __restrict__ b3,
               const float* __restrict__ G1, const float* __restrict__ gb1,
               const float* __restrict__ G2, const float* __restrict__ gb2,
               const float* __restrict__ R1, const float* __restrict__ rb1,
               const float* __restrict__ R2, const float* __restrict__ rb2,
               float* __restrict__ out)
{
    const int tid  = threadIdx.x;
    const int wid  = tid >> 5;     // warp 0..3, owns experts 2w, 2w+1
    const int lane = tid & 31;
    const int grp  = lane >> 2;
    const int tig  = lane & 3;
    const u32 sbase = smem_to_u32(smem_raw);

    // ---- expert bias2 packed table (128 threads cover 8 experts) ----
    {
        int te = tid >> 4, tn = (tid >> 2) & 3, tg = tid & 3;
        int c0 = tn * 8 + 2 * tg;
        *reinterpret_cast<u32*>(smem_raw + TB2 + tid * 4) =
            f16pk(b2[te * 32 + c0], b2[te * 32 + c0 + 1]);
    }

    // ---- gate / refine per-lane fragment tables (272B stride) ----
    if (tid < 32) {
        int g = tid >> 2, t = tid & 3;
        int k0 = 2 * t;
        {
            char* gt = smem_raw + GT + tid * 272;
            u32*    b1t = reinterpret_cast<u32*>(gt);
            u32*    c1p = reinterpret_cast<u32*>(gt + 64);
            u32*    b2t = reinterpret_cast<u32*>(gt + 96);
            float2* c2t = reinterpret_cast<float2*>(gt + 128);
            #pragma unroll
            for (int nt = 0; nt < 8; nt++) {
                int n = nt * 8 + g;
                b1t[nt * 2]     = f16pk(G1[k0 * 64 + n], G1[(k0 + 1) * 64 + n]);
                float wa = (k0 + 8 < 10) ? G1[(k0 + 8) * 64 + n] : 0.f;
                float wb = (k0 + 9 < 10) ? G1[(k0 + 9) * 64 + n] : 0.f;
                b1t[nt * 2 + 1] = f16pk(wa, wb);
                c1p[nt] = f16pk(gb1[nt * 8 + k0], gb1[nt * 8 + k0 + 1]);
            }
            #pragma unroll
            for (int kt = 0; kt < 4; kt++) {
                int kk = kt * 16 + k0;
                b2t[kt * 2]     = f16pk(G2[kk * 8 + g],       G2[(kk + 1) * 8 + g]);
                b2t[kt * 2 + 1] = f16pk(G2[(kk + 8) * 8 + g], G2[(kk + 9) * 8 + g]);
            }
            c2t[0] = make_float2(gb2[k0], gb2[k0 + 1]);
        }
        {
            char* rt = smem_raw + RT + tid * 272;
            u32*    b1t = reinterpret_cast<u32*>(rt);
            u32*    c1p = reinterpret_cast<u32*>(rt + 64);
            u32*    b2t = reinterpret_cast<u32*>(rt + 96);
            float2* c2t = reinterpret_cast<float2*>(rt + 128);
            #pragma unroll
            for (int nt = 0; nt < 8; nt++) {
                int n = nt * 8 + g;
                b1t[nt * 2]     = f16pk(R1[k0 * 64 + n], R1[(k0 + 1) * 64 + n]);
                float wa = (k0 + 8 < 12) ? R1[(k0 + 8) * 64 + n] : 0.f;
                float wb = (k0 + 9 < 12) ? R1[(k0 + 9) * 64 + n] : 0.f;
                b1t[nt * 2 + 1] = f16pk(wa, wb);
                c1p[nt] = f16pk(rb1[nt * 8 + k0], rb1[nt * 8 + k0 + 1]);
            }
            #pragma unroll
            for (int kt = 0; kt < 4; kt++) {
                int kk = kt * 16 + k0;
                float wa0 = (g < 2) ? R2[kk * 2 + g] : 0.f;
                float wb0 = (g < 2) ? R2[(kk + 1) * 2 + g] : 0.f;
                b2t[kt * 2]     = f16pk(wa0, wb0);
                float wa1 = (g < 2) ? R2[(kk + 8) * 2 + g] : 0.f;
                float wb1 = (g < 2) ? R2[(kk + 9) * 2 + g] : 0.f;
                b2t[kt * 2 + 1] = f16pk(wa1, wb1);
            }
            c2t[0] = make_float2(t == 0 ? rb2[0] : 0.f, t == 0 ? rb2[1] : 0.f);
        }
    }

    // ---- register-resident fp16 fragments for BOTH experts of this warp ----
    u32 b1f[2][4][2];
    u32 b2f[2][4][2][2];
    u32 w3f[2][2][2];
    u32 bias1p[2][4];
    float b3e[2][2];
    #pragma unroll
    for (int p = 0; p < 2; p++) {
        const int e = wid * 2 + p;
        #pragma unroll
        for (int nt = 0; nt < 4; nt++) {
            int n = nt * 8 + grp;
            b1f[p][nt][0] = f16pk(W1[e * 320 + (2 * tig) * 32 + n],
                                  W1[e * 320 + (2 * tig + 1) * 32 + n]);
            {
                float wa = (2 * tig + 8 < 10) ? W1[e * 320 + (2 * tig + 8) * 32 + n] : 0.f;
                float wb = (2 * tig + 9 < 10) ? W1[e * 320 + (2 * tig + 9) * 32 + n] : 0.f;
                b1f[p][nt][1] = f16pk(wa, wb);
            }
            #pragma unroll
            for (int kt = 0; kt < 2; kt++) {
                int k0 = kt * 16 + 2 * tig;
                b2f[p][nt][kt][0] = f16pk(W2[e * 1024 + k0 * 32 + n],
                                          W2[e * 1024 + (k0 + 1) * 32 + n]);
                b2f[p][nt][kt][1] = f16pk(W2[e * 1024 + (k0 + 8) * 32 + n],
                                          W2[e * 1024 + (k0 + 9) * 32 + n]);
            }
            int c0 = nt * 8 + 2 * tig;
            bias1p[p][nt] = f16pk(b1[e * 32 + c0], b1[e * 32 + c0 + 1]);
        }
        #pragma unroll
        for (int kc = 0; kc < 2; kc++) {
            int kb = kc * 16;
            float v00 = (grp < 2) ? W3[e * 64 + (kb + 2 * tig) * 2 + grp] : 0.f;
            float v01 = (grp < 2) ? W3[e * 64 + (kb + 2 * tig + 1) * 2 + grp] : 0.f;
            w3f[p][kc][0] = f16pk(v00, v01);
            float v10 = (grp < 2) ? W3[e * 64 + (kb + 8 + 2 * tig) * 2 + grp] : 0.f;
            float v11 = (grp < 2) ? W3[e * 64 + (kb + 9 + 2 * tig) * 2 + grp] : 0.f;
            w3f[p][kc][1] = f16pk(v10, v11);
        }
        b3e[p][0] = b3[e * 2]; b3e[p][1] = b3[e * 2 + 1];
    }
    __syncthreads();

    // hoisted bias2 fragments for both experts
    u32 tb2r[2][4];
    #pragma unroll
    for (int p = 0; p < 2; p++)
        #pragma unroll
        for (int nt = 0; nt < 4; nt++)
            tb2r[p][nt] = *reinterpret_cast<const u32*>(
                smem_raw + TB2 + (u32)((((wid * 2 + p) * 4 + nt) * 4 + tig)) * 4);

    for (int tile = blockIdx.x; tile < NTILES; tile += gridDim.x) {

        // ============ phase 1: load x for 2 tokens, stage fp16 rows ============
        #pragma unroll
        for (int h = 0; h < 2; h++) {
            const int t = tid + h * 128;
            const float2* xp = reinterpret_cast<const float2*>(
                X + (size_t)(tile * 256 + t) * 10);
            u32 xs[5];
            #pragma unroll
            for (int i = 0; i < 5; i++) {
                float2 v = xp[i];
                xs[i] = f16pk(v.x, v.y);
            }
            uint4* pr = reinterpret_cast<uint4*>(smem_raw + XB + t * 48);
            pr[0] = make_uint4(xs[0], xs[1], xs[2], xs[3]);
            pr[1] = make_uint4(xs[4], 0u, 0u, 0u);
        }
        __syncthreads();

        // ============ phase 2a: gate via mma (4 m-tiles per warp) ============
        {
            const char* gt = smem_raw + GT + (u32)lane * 272;
            const u32*    b1t = reinterpret_cast<const u32*>(gt);
            const u32*    c1p = reinterpret_cast<const u32*>(gt + 64);
            const u32*    b2t = reinterpret_cast<const u32*>(gt + 96);
            const float2  c2  = *reinterpret_cast<const float2*>(gt + 128);
            float* wxp = reinterpret_cast<float*>(smem_raw + WX);
            #pragma unroll 1
            for (int q = 0; q < 4; q++) {
                int mt = wid * 4 + q;
                u32 ax[4];
                ldm_x4(ax, sbase + XB + (u32)(mt * 16 + (lane & 15)) * 48
                           + ((lane >> 4) << 4));
                u32 a2[4][4];
                #pragma unroll
                for (int nt = 0; nt < 8; nt++) {
                    u32 dh0, dh1;
                    mma_h16_c(dh0, dh1, ax[0], ax[1], ax[2], ax[3],
                              b1t[2*nt], b1t[2*nt+1], c1p[nt]);
                    int kt = nt >> 1, hf = (nt & 1) << 1;
                    a2[kt][hf]     = max0_pk(dh0);
                    a2[kt][hf + 1] = max0_pk(dh1);
                }
                float l0, l1, l2, l3;
                mma_f16_c(l0, l1, l2, l3,
                          a2[0][0], a2[0][1], a2[0][2], a2[0][3],
                          b2t[0], b2t[1], c2.x, c2.y);
                #pragma unroll
                for (int kt = 1; kt < 4; kt++)
                    mma_f16_acc(l0, l1, l2, l3,
                                a2[kt][0], a2[kt][1], a2[kt][2], a2[kt][3],
                                b2t[2*kt], b2t[2*kt+1]);
                float mA = fmaxf(l0, l1);
                mA = fmaxf(mA, __shfl_xor_sync(0xFFFFFFFFu, mA, 1));
                mA = fmaxf(mA, __shfl_xor_sync(0xFFFFFFFFu, mA, 2));
                float eA0 = __expf(l0 - mA), eA1 = __expf(l1 - mA);
                float sA = eA0 + eA1;
                sA += __shfl_xor_sync(0xFFFFFFFFu, sA, 1);
                sA += __shfl_xor_sync(0xFFFFFFFFu, sA, 2);
                float iA = __fdividef(1.f, sA);
                float mB = fmaxf(l2, l3);
                mB = fmaxf(mB, __shfl_xor_sync(0xFFFFFFFFu, mB, 1));
                mB = fmaxf(mB, __shfl_xor_sync(0xFFFFFFFFu, mB, 2));
                float eB0 = __expf(l2 - mB), eB1 = __expf(l3 - mB);
                float sB = eB0 + eB1;
                sB += __shfl_xor_sync(0xFFFFFFFFu, sB, 1);
                sB += __shfl_xor_sync(0xFFFFFFFFu, sB, 2);
                float iB = __fdividef(1.f, sB);
                int rowA = mt * 16 + grp;
                wxp[(2*tig)   * 256 + rowA]     = eA0 * iA;
                wxp[(2*tig+1) * 256 + rowA]     = eA1 * iA;
                wxp[(2*tig)   * 256 + rowA + 8] = eB0 * iB;
                wxp[(2*tig+1) * 256 + rowA + 8] = eB1 * iB;
            }
        }

        // ======== phase 2b: expert GEMMs — 2 independent chains per warp ========
        {
            float2* fup = reinterpret_cast<float2*>(smem_raw + FU);
            #pragma unroll 1
            for (int mt = 0; mt < 16; mt++) {
                u32 ax[4];
                ldm_x4(ax, sbase + XB + (u32)(mt * 16 + (lane & 15)) * 48
                           + ((lane >> 4) << 4));
                // L1 for both experts
                u32 a2[2][2][4];
                #pragma unroll
                for (int p = 0; p < 2; p++)
                    #pragma unroll
                    for (int nt = 0; nt < 4; nt++) {
                        u32 dh0, dh1;
                        mma_h16_c(dh0, dh1, ax[0], ax[1], ax[2], ax[3],
                                  b1f[p][nt][0], b1f[p][nt][1], bias1p[p][nt]);
                        int kt = nt >> 1, hf = (nt & 1) << 1;
                        a2[p][kt][hf]     = max0_pk(dh0);
                        a2[p][kt][hf + 1] = max0_pk(dh1);
                    }
                // L2 for both experts
                u32 p3[2][4][2];
                #pragma unroll
                for (int p = 0; p < 2; p++)
                    #pragma unroll
                    for (int nt = 0; nt < 4; nt++) {
                        u32 gh0, gh1;
                        mma_h16_c(gh0, gh1,
                                  a2[p][0][0], a2[p][0][1], a2[p][0][2], a2[p][0][3],
                                  b2f[p][nt][0][0], b2f[p][nt][0][1], tb2r[p][nt]);
                        mma_h16_acc(gh0, gh1,
                                    a2[p][1][0], a2[p][1][1], a2[p][1][2], a2[p][1][3],
                                    b2f[p][nt][1][0], b2f[p][nt][1][1]);
                        p3[p][nt][0] = max0_pk(gh0);
                        p3[p][nt][1] = max0_pk(gh1);
                    }
                // L3 for both experts
                #pragma unroll
                for (int p = 0; p < 2; p++) {
                    float y0, y1, y2, y3;
                    mma_f16_c(y0, y1, y2, y3,
                              p3[p][0][0], p3[p][0][1], p3[p][1][0], p3[p][1][1],
                              w3f[p][0][0], w3f[p][0][1], b3e[p][0], b3e[p][1]);
                    mma_f16_acc(y0, y1, y2, y3,
                                p3[p][2][0], p3[p][2][1], p3[p][3][0], p3[p][3][1],
                                w3f[p][1][0], w3f[p][1][1]);
                    if (tig == 0) {
                        int tk = mt * 16 + grp;
                        int e = wid * 2 + p;
                        fup[e * 256 + tk]     = make_float2(y0, y1);
                        fup[e * 256 + tk + 8] = make_float2(y2, y3);
                    }
                }
            }
        }
        __syncthreads();

        // ===== phase 3: tanh + fuse + restage rin (2 tokens per thread) =====
        {
            const float2* fup = reinterpret_cast<const float2*>(smem_raw + FU);
            const float* wxp = reinterpret_cast<const float*>(smem_raw + WX);
            #pragma unroll
            for (int h = 0; h < 2; h++) {
                const int t = tid + h * 128;
                float f0 = 0.f, f1 = 0.f;
                #pragma unroll
                for (int q2 = 0; q2 < 8; q2++) {
                    float2 s = fup[q2 * 256 + t];
                    float w = wxp[q2 * 256 + t];
                    f0 += w * tanh_acc(s.x);
                    f1 += w * tanh_acc(s.y);
                }
                const uint4* xr = reinterpret_cast<const uint4*>(smem_raw + XB + t * 48);
                uint4 v0 = xr[0], v1 = xr[1];
                uint4* pr = reinterpret_cast<uint4*>(smem_raw + RB + t * 48);
                pr[0] = make_uint4(f16pk(f0, f1), v0.x, v0.y, v0.z);
                pr[1] = make_uint4(v0.w, v1.x, 0u, 0u);
            }
        }
        __syncthreads();

        // ============ phase 4: refine via mma (4 m-tiles per warp) ============
        {
            const char* rt = smem_raw + RT + (u32)lane * 272;
            const u32*    b1t = reinterpret_cast<const u32*>(rt);
            const u32*    c1p = reinterpret_cast<const u32*>(rt + 64);
            const u32*    b2t = reinterpret_cast<const u32*>(rt + 96);
            const float2  c2  = *reinterpret_cast<const float2*>(rt + 128);
            float2* out2 = reinterpret_cast<float2*>(out);
            #pragma unroll 1
            for (int q = 0; q < 4; q++) {
                int mt = wid * 4 + q;
                u32 ax[4];
                ldm_x4(ax, sbase + RB + (u32)(mt * 16 + (lane & 15)) * 48
                           + ((lane >> 4) << 4));
                u32 a2[4][4];
                #pragma unroll
                for (int nt = 0; nt < 8; nt++) {
                    u32 dh0, dh1;
                    mma_h16_c(dh0, dh1, ax[0], ax[1], ax[2], ax[3],
                              b1t[2*nt], b1t[2*nt+1], c1p[nt]);
                    int kt = nt >> 1, hf = (nt & 1) << 1;
                    a2[kt][hf]     = max0_pk(dh0);
                    a2[kt][hf + 1] = max0_pk(dh1);
                }
                float y0, y1, y2, y3;
                mma_f16_c(y0, y1, y2, y3,
                          a2[0][0], a2[0][1], a2[0][2], a2[0][3],
                          b2t[0], b2t[1], c2.x, c2.y);
                #pragma unroll
                for (int kt = 1; kt < 4; kt++)
                    mma_f16_acc(y0, y1, y2, y3,
                                a2[kt][0], a2[kt][1], a2[kt][2], a2[kt][3],
                                b2t[2*kt], b2t[2*kt+1]);
                if (tig == 0) {
                    int rowA = tile * 256 + mt * 16 + grp;
                    out2[rowA]     = make_float2(tanh_acc(y0), tanh_acc(y1));
                    out2[rowA + 8] = make_float2(tanh_acc(y2), tanh_acc(y3));
                }
            }
        }
    }
}

extern "C" void kernel_launch(void* const* d_in, const int* in_sizes, int n_in,
                              void* d_out, int out_size)
{
    (void)in_sizes; (void)n_in; (void)out_size;
    const float* X   = (const float*)d_in[0];
    const float* W1  = (const float*)d_in[1];
    const float* b1  = (const float*)d_in[2];
    const float* W2  = (const float*)d_in[3];
    const float* b2  = (const float*)d_in[4];
    const float* W3  = (const float*)d_in[5];
    const float* b3  = (const float*)d_in[6];
    const float* G1  = (const float*)d_in[7];
    const float* gb1 = (const float*)d_in[8];
    const float* G2  = (const float*)d_in[9];
    const float* gb2 = (const float*)d_in[10];
    const float* R1  = (const float*)d_in[11];
    const float* rb1 = (const float*)d_in[12];
    const float* R2  = (const float*)d_in[13];
    const float* rb2 = (const float*)d_in[14];

    cudaFuncSetAttribute(moe_r17_kernel,
                         cudaFuncAttributeMaxDynamicSharedMemorySize, SMEM_TOTAL);

    moe_r17_kernel<<<GRID, 128, SMEM_TOTAL>>>(
        X, W1, b1, W2, b2, W3, b3, G1, gb1, G2, gb2, R1, rb1, R2, rb2,
        (float*)d_out);
}